// round 3
// baseline (speedup 1.0000x reference)
#include <cuda_runtime.h>
#include <cstdint>

// ---------------- problem constants ----------------
#define BATCH   128
#define DIM     384
#define RES     14
#define NPIX    196
#define HEADS   8
#define KD      32
#define DV      128
#define DH      1024
#define OCQKV   1536
#define SCALE_ATTN 0.17677669529663687f
#define NPAD    208
#define SPAD    208              // padded S dims (rows & cols)
#define QSTR    212              // smem row stride for s_kernel operands
#define MSTR    212              // smem row stride for mix kernel

// ---------------- device scratch ----------------
__device__ float g_qkv [(size_t)BATCH * OCQKV * NPIX];
__device__ float g_vloc[(size_t)BATCH * DH * NPIX];
__device__ float g_xout[(size_t)BATCH * DH * NPIX];
__device__ float g_S   [(size_t)BATCH * HEADS * SPAD * SPAD];
__device__ float g_wqkv[OCQKV * DIM];
__device__ float g_bqkv[OCQKV];
__device__ float g_wproj[DIM * DH];
__device__ float g_bproj[DIM];
__device__ float g_wvl[DH * 9];
__device__ float g_bvl[DH];
__device__ float g_bias[HEADS * NPIX * NPIX];

// ---------------- tf32 helpers ----------------
__device__ __forceinline__ uint32_t f2tf(float f) {
    uint32_t u; asm("cvt.rna.tf32.f32 %0, %1;" : "=r"(u) : "f"(f)); return u;
}
__device__ __forceinline__ void mma8(float* c, uint32_t a0, uint32_t a1, uint32_t a2, uint32_t a3,
                                     uint32_t b0, uint32_t b1) {
    asm volatile(
        "mma.sync.aligned.m16n8k8.row.col.f32.tf32.tf32.f32 "
        "{%0,%1,%2,%3},{%4,%5,%6,%7},{%8,%9},{%0,%1,%2,%3};"
        : "+f"(c[0]), "+f"(c[1]), "+f"(c[2]), "+f"(c[3])
        : "r"(a0), "r"(a1), "r"(a2), "r"(a3), "r"(b0), "r"(b1));
}

// ---------------- BN folding ----------------
__global__ void fold_qkv_kernel(
    const float* __restrict__ q_w, const float* __restrict__ q_b,
    const float* __restrict__ q_s, const float* __restrict__ q_t,
    const float* __restrict__ k_w, const float* __restrict__ k_b,
    const float* __restrict__ k_s, const float* __restrict__ k_t,
    const float* __restrict__ v_w, const float* __restrict__ v_b,
    const float* __restrict__ v_s, const float* __restrict__ v_t)
{
    int idx = blockIdx.x * blockDim.x + threadIdx.x;
    if (idx >= OCQKV * DIM) return;
    int oc = idx / DIM, c = idx - oc * DIM;
    float w, s;
    if (oc < 256) {
        w = q_w[oc * DIM + c]; s = q_s[oc] * SCALE_ATTN;
        if (c == 0) g_bqkv[oc] = (q_b[oc] * q_s[oc] + q_t[oc]) * SCALE_ATTN;
    } else if (oc < 512) {
        int o = oc - 256;
        w = k_w[o * DIM + c]; s = k_s[o];
        if (c == 0) g_bqkv[oc] = k_b[o] * k_s[o] + k_t[o];
    } else {
        int o = oc - 512;
        w = v_w[o * DIM + c]; s = v_s[o];
        if (c == 0) g_bqkv[oc] = v_b[o] * v_s[o] + v_t[o];
    }
    g_wqkv[idx] = w * s;
}

__global__ void fold_proj_kernel(
    const float* __restrict__ p_w, const float* __restrict__ p_b,
    const float* __restrict__ p_s, const float* __restrict__ p_t)
{
    int idx = blockIdx.x * blockDim.x + threadIdx.x;
    if (idx >= DIM * DH) return;
    int oc = idx / DH;
    g_wproj[idx] = p_w[idx] * p_s[oc];
    if ((idx - oc * DH) == 0) g_bproj[oc] = p_b[oc] * p_s[oc] + p_t[oc];
}

__global__ void fold_vl_kernel(
    const float* __restrict__ vl_w, const float* __restrict__ vl_b,
    const float* __restrict__ vl_s, const float* __restrict__ vl_t)
{
    int idx = blockIdx.x * blockDim.x + threadIdx.x;
    if (idx >= DH * 9) return;
    int ch = idx / 9;
    g_wvl[idx] = vl_w[idx] * vl_s[ch];
    if (idx == ch * 9) g_bvl[ch] = vl_b[ch] * vl_s[ch] + vl_t[ch];
}

__global__ void bias_expand_kernel(const float* __restrict__ bias_seg,
                                   const int* __restrict__ bias_idxs, int n_off)
{
    int e = blockIdx.x * blockDim.x + threadIdx.x;
    if (e >= HEADS * NPIX * NPIX) return;
    int h = e / (NPIX * NPIX), nm = e - h * (NPIX * NPIX);
    g_bias[e] = bias_seg[h * n_off + bias_idxs[nm]];
}

// ---------------- tf32 mma GEMM: Y[b][oc][n] = W @ X + bias ----------------
#define BKG 32
template<int MODE>
__global__ __launch_bounds__(512, 1)
void gemm_mma(const float* __restrict__ Xin, float* __restrict__ Yout)
{
    const int K = (MODE == 0) ? DIM : DH;
    const float* __restrict__ W  = (MODE == 0) ? g_wqkv : g_wproj;
    const float* __restrict__ Bv = (MODE == 0) ? g_bqkv : g_bproj;
    const int b = blockIdx.x, oc0 = blockIdx.y * 128;
    const float* Xb = ((MODE == 0) ? Xin : g_xout) + (size_t)b * K * NPIX;
    float*       Yb = ((MODE == 0) ? g_qkv : Yout) + (size_t)b * ((MODE == 0) ? OCQKV : DIM) * NPIX;

    __shared__ uint32_t sW[BKG][129];
    __shared__ uint32_t sX[BKG][216];

    const int tid = threadIdx.x, lane = tid & 31, w = tid >> 5;
    const int ocg = w >> 1, half = w & 1, g = lane >> 2, q = lane & 3;
    const int ob = ocg * 16;

    float c[13][4];
    #pragma unroll
    for (int t = 0; t < 13; ++t) { c[t][0] = c[t][1] = c[t][2] = c[t][3] = 0.f; }

    for (int k0 = 0; k0 < K; k0 += BKG) {
        for (int e = tid; e < 128 * BKG; e += 512) {
            int oc = e >> 5, kk = e & 31;
            sW[kk][oc] = f2tf(W[(size_t)(oc0 + oc) * K + k0 + kk]);
        }
        for (int e = tid; e < BKG * NPAD; e += 512) {
            int kk = e / NPAD, n = e - kk * NPAD;
            sX[kk][n] = (n < NPIX) ? f2tf(Xb[(size_t)(k0 + kk) * NPIX + n]) : 0u;
        }
        __syncthreads();
        #pragma unroll
        for (int kk = 0; kk < 4; ++kk) {
            int cb = kk * 8;
            uint32_t a0 = sW[cb + q][ob + g],     a1 = sW[cb + q][ob + g + 8];
            uint32_t a2 = sW[cb + q + 4][ob + g], a3 = sW[cb + q + 4][ob + g + 8];
            #pragma unroll
            for (int t = 0; t < 13; ++t) {
                int n = (half * 13 + t) * 8 + g;
                mma8(c[t], a0, a1, a2, a3, sX[cb + q][n], sX[cb + q + 4][n]);
            }
        }
        __syncthreads();
    }

    int r1 = oc0 + ob + g, r2 = r1 + 8;
    float bb1 = Bv[r1], bb2 = Bv[r2];
    #pragma unroll
    for (int t = 0; t < 13; ++t) {
        int n0 = (half * 13 + t) * 8 + 2 * q;
        if (n0 < NPIX) {
            *(float2*)(Yb + (size_t)r1 * NPIX + n0) = make_float2(c[t][0] + bb1, c[t][1] + bb1);
            *(float2*)(Yb + (size_t)r2 * NPIX + n0) = make_float2(c[t][2] + bb2, c[t][3] + bb2);
        }
    }
}

// ---------------- depthwise 3x3 local-V ----------------
__global__ __launch_bounds__(224)
void vloc_kernel()
{
    int blk = blockIdx.x;
    int b = blk >> 10, ch = blk & 1023;
    __shared__ float sp[NPIX];
    __shared__ float swv[9];
    int t = threadIdx.x;
    const float* src = g_qkv + (size_t)b * OCQKV * NPIX + (size_t)(512 + ch) * NPIX;
    if (t < NPIX) sp[t] = src[t];
    if (t < 9)  swv[t] = g_wvl[ch * 9 + t];
    __syncthreads();
    if (t < NPIX) {
        int i = t / RES, j = t - i * RES;
        float acc = g_bvl[ch];
        #pragma unroll
        for (int di = 0; di < 3; ++di) {
            int ii = i + di - 1;
            if (ii < 0 || ii >= RES) continue;
            #pragma unroll
            for (int dj = 0; dj < 3; ++dj) {
                int jj = j + dj - 1;
                if (jj < 0 || jj >= RES) continue;
                acc += sp[ii * RES + jj] * swv[di * 3 + dj];
            }
        }
        g_vloc[(size_t)b * DH * NPIX + (size_t)ch * NPIX + t] = acc;
    }
}

// ---------------- S = Q^T K + bias, per (b,h) -> g_S (208x208, zero-padded) ----------------
#define S_SMEM (2 * 32 * QSTR * 4)
__global__ __launch_bounds__(512, 1)
void s_kernel()
{
    extern __shared__ uint32_t sqk[];
    uint32_t* sQ = sqk;                // [c][n] tf32
    uint32_t* sK = sqk + 32 * QSTR;

    const int b = blockIdx.x, h = blockIdx.y;
    const int tid = threadIdx.x, lane = tid & 31, w = tid >> 5;
    const int g = lane >> 2, q = lane & 3;
    const size_t base = (size_t)b * OCQKV * NPIX;
    const float* Qp = g_qkv + base + (size_t)(h * KD) * NPIX;
    const float* Kp = g_qkv + base + (size_t)(256 + h * KD) * NPIX;

    for (int e = tid; e < 32 * QSTR; e += 512) {
        int c = e / QSTR, n = e - c * QSTR;
        uint32_t qv = 0u, kv = 0u;
        if (n < NPIX) { qv = f2tf(Qp[c * NPIX + n]); kv = f2tf(Kp[c * NPIX + n]); }
        sQ[e] = qv; sK[e] = kv;
    }
    __syncthreads();

    float* Sp = g_S + (size_t)(b * HEADS + h) * (SPAD * SPAD);
    const float* bh = g_bias + h * NPIX * NPIX;

    for (int t = w; t < 13 * 26; t += 16) {
        int mb = t / 26, nb = t - mb * 26;
        int r1 = mb * 16 + g, r2 = r1 + 8;
        int ncol = nb * 8 + g;
        float c4[4] = {0.f, 0.f, 0.f, 0.f};
        #pragma unroll
        for (int kk = 0; kk < 4; ++kk) {
            int cb = kk * 8;
            uint32_t a0 = sQ[(cb + q) * QSTR + r1],     a1 = sQ[(cb + q) * QSTR + r2];
            uint32_t a2 = sQ[(cb + q + 4) * QSTR + r1], a3 = sQ[(cb + q + 4) * QSTR + r2];
            mma8(c4, a0, a1, a2, a3, sK[(cb + q) * QSTR + ncol], sK[(cb + q + 4) * QSTR + ncol]);
        }
        int m0 = nb * 8 + 2 * q;
        float v0 = c4[0], v1 = c4[1], v2 = c4[2], v3 = c4[3];
        if (m0 < NPIX) {
            if (r1 < NPIX) { v0 += bh[r1 * NPIX + m0]; v1 += bh[r1 * NPIX + m0 + 1]; }
            if (r2 < NPIX) { v2 += bh[r2 * NPIX + m0]; v3 += bh[r2 * NPIX + m0 + 1]; }
        }
        *(float2*)(Sp + (size_t)r1 * SPAD + m0) = make_float2(v0, v1);
        *(float2*)(Sp + (size_t)r2 * SPAD + m0) = make_float2(v2, v3);
    }
}

// ---------------- mix1 + softmax + mix2, in-place on g_S ----------------
#define MIX_SMEM (HEADS * 14 * MSTR * 4)
__global__ __launch_bounds__(512, 1)
void mix_kernel(const float* __restrict__ th1_w, const float* __restrict__ th1_b,
                const float* __restrict__ th2_w, const float* __restrict__ th2_b)
{
    extern __shared__ float sm[];     // [8][14][MSTR]
    __shared__ float sTh1[64], sTh1b[8], sTh2[64], sTh2b[8];

    const int b = blockIdx.x, chunk = blockIdx.y;
    const int n0 = chunk * 14;
    const int tid = threadIdx.x, lane = tid & 31, w = tid >> 5;

    if (tid < 64) { sTh1[tid] = th1_w[tid]; sTh2[tid] = th2_w[tid]; }
    if (tid < 8)  { sTh1b[tid] = th1_b[tid]; sTh2b[tid] = th2_b[tid]; }

    const size_t sb = (size_t)(b * HEADS) * (SPAD * SPAD);
    for (int e = tid; e < HEADS * 14 * SPAD; e += 512) {
        int h = e / (14 * SPAD), rem = e - h * (14 * SPAD);
        int r = rem / SPAD, m = rem - r * SPAD;
        sm[(h * 14 + r) * MSTR + m] = g_S[sb + (size_t)h * (SPAD * SPAD) + (size_t)(n0 + r) * SPAD + m];
    }
    __syncthreads();

    // mix1
    for (int e = tid; e < 14 * NPIX; e += 512) {
        int r = e / NPIX, m = e - r * NPIX;
        float sv[8];
        #pragma unroll
        for (int i = 0; i < 8; ++i) sv[i] = sm[(i * 14 + r) * MSTR + m];
        #pragma unroll
        for (int o = 0; o < 8; ++o) {
            float a = sTh1b[o];
            #pragma unroll
            for (int i = 0; i < 8; ++i) a += sTh1[o * 8 + i] * sv[i];
            sm[(o * 14 + r) * MSTR + m] = a;
        }
    }
    __syncthreads();

    // softmax over m<196, per row; 112 rows over 16 warps
    for (int row = w; row < HEADS * 14; row += 16) {
        float* p = sm + row * MSTR;
        float mx = -1e30f;
        for (int m = lane; m < NPIX; m += 32) mx = fmaxf(mx, p[m]);
        #pragma unroll
        for (int o = 16; o; o >>= 1) mx = fmaxf(mx, __shfl_xor_sync(~0u, mx, o));
        float s = 0.f;
        for (int m = lane; m < NPIX; m += 32) { float ev = __expf(p[m] - mx); p[m] = ev; s += ev; }
        #pragma unroll
        for (int o = 16; o; o >>= 1) s += __shfl_xor_sync(~0u, s, o);
        float inv = 1.f / s;
        for (int m = lane; m < NPIX; m += 32) p[m] *= inv;
    }
    __syncthreads();

    // mix2
    for (int e = tid; e < 14 * NPIX; e += 512) {
        int r = e / NPIX, m = e - r * NPIX;
        float sv[8];
        #pragma unroll
        for (int i = 0; i < 8; ++i) sv[i] = sm[(i * 14 + r) * MSTR + m];
        #pragma unroll
        for (int o = 0; o < 8; ++o) {
            float a = sTh2b[o];
            #pragma unroll
            for (int i = 0; i < 8; ++i) a += sTh2[o * 8 + i] * sv[i];
            sm[(o * 14 + r) * MSTR + m] = a;
        }
    }
    __syncthreads();

    // write back, zero pad cols m>=196
    for (int e = tid; e < HEADS * 14 * SPAD; e += 512) {
        int h = e / (14 * SPAD), rem = e - h * (14 * SPAD);
        int r = rem / SPAD, m = rem - r * SPAD;
        float v = (m < NPIX) ? sm[(h * 14 + r) * MSTR + m] : 0.f;
        g_S[sb + (size_t)h * (SPAD * SPAD) + (size_t)(n0 + r) * SPAD + m] = v;
    }
}

// ---------------- out[d][n] = V @ P^T per (b,h), fused +vloc +relu ----------------
__global__ __launch_bounds__(512, 1)
void av_kernel()
{
    __shared__ uint32_t sA[16][136];   // V  [k(m)][d]
    __shared__ uint32_t sB[16][216];   // P  [k(m)][n]

    const int b = blockIdx.x, h = blockIdx.y;
    const int tid = threadIdx.x, lane = tid & 31, w = tid >> 5;
    const int ob = (w >> 1) * 16, half = w & 1, g = lane >> 2, q = lane & 3;
    const float* Vp = g_qkv + (size_t)b * OCQKV * NPIX + (size_t)(512 + h * DV) * NPIX;
    const float* Pp = g_S + (size_t)(b * HEADS + h) * (SPAD * SPAD);
    const size_t xob = (size_t)b * DH * NPIX;

    float c[13][4];
    #pragma unroll
    for (int t = 0; t < 13; ++t) { c[t][0] = c[t][1] = c[t][2] = c[t][3] = 0.f; }

    for (int k0 = 0; k0 < SPAD; k0 += 16) {
        for (int e = tid; e < DV * 16; e += 512) {
            int d = e >> 4, kk = e & 15;
            int m = k0 + kk;
            sA[kk][d] = (m < NPIX) ? f2tf(Vp[d * NPIX + m]) : 0u;
        }
        for (int e = tid; e < SPAD * 16; e += 512) {
            int n = e >> 4, kk = e & 15;
            sB[kk][n] = f2tf(Pp[(size_t)n * SPAD + k0 + kk]);
        }
        __syncthreads();
        #pragma unroll
        for (int kk = 0; kk < 2; ++kk) {
            int cb = kk * 8;
            uint32_t a0 = sA[cb + q][ob + g],     a1 = sA[cb + q][ob + g + 8];
            uint32_t a2 = sA[cb + q + 4][ob + g], a3 = sA[cb + q + 4][ob + g + 8];
            #pragma unroll
            for (int t = 0; t < 13; ++t) {
                int n = (half * 13 + t) * 8 + g;
                mma8(c[t], a0, a1, a2, a3, sB[cb + q][n], sB[cb + q + 4][n]);
            }
        }
        __syncthreads();
    }

    int d1 = ob + g, d2 = d1 + 8;
    size_t o1 = xob + (size_t)(h * DV + d1) * NPIX;
    size_t o2 = xob + (size_t)(h * DV + d2) * NPIX;
    #pragma unroll
    for (int t = 0; t < 13; ++t) {
        int n0 = (half * 13 + t) * 8 + 2 * q;
        if (n0 < NPIX) {
            float u0 = fmaxf(c[t][0] + g_vloc[o1 + n0], 0.f);
            float u1 = fmaxf(c[t][1] + g_vloc[o1 + n0 + 1], 0.f);
            float u2 = fmaxf(c[t][2] + g_vloc[o2 + n0], 0.f);
            float u3 = fmaxf(c[t][3] + g_vloc[o2 + n0 + 1], 0.f);
            *(float2*)(g_xout + o1 + n0) = make_float2(u0, u1);
            *(float2*)(g_xout + o2 + n0) = make_float2(u2, u3);
        }
    }
}

// ---------------- host launch ----------------
extern "C" void kernel_launch(void* const* d_in, const int* in_sizes, int n_in,
                              void* d_out, int out_size)
{
    const float* x        = (const float*)d_in[0];
    const float* q_w      = (const float*)d_in[1];
    const float* q_b      = (const float*)d_in[2];
    const float* q_s      = (const float*)d_in[3];
    const float* q_t      = (const float*)d_in[4];
    const float* k_w      = (const float*)d_in[5];
    const float* k_b      = (const float*)d_in[6];
    const float* k_s      = (const float*)d_in[7];
    const float* k_t      = (const float*)d_in[8];
    const float* v_w      = (const float*)d_in[9];
    const float* v_b      = (const float*)d_in[10];
    const float* v_s      = (const float*)d_in[11];
    const float* v_t      = (const float*)d_in[12];
    const float* vl_w     = (const float*)d_in[13];
    const float* vl_b     = (const float*)d_in[14];
    const float* vl_s     = (const float*)d_in[15];
    const float* vl_t     = (const float*)d_in[16];
    const float* th1_w    = (const float*)d_in[17];
    const float* th1_b    = (const float*)d_in[18];
    const float* th2_w    = (const float*)d_in[19];
    const float* th2_b    = (const float*)d_in[20];
    const float* proj_w   = (const float*)d_in[21];
    const float* proj_b   = (const float*)d_in[22];
    const float* proj_s   = (const float*)d_in[23];
    const float* proj_t   = (const float*)d_in[24];
    const float* bias_seg = (const float*)d_in[25];
    const int*   bias_idx = (const int*)  d_in[26];
    float*       out      = (float*)d_out;

    const int n_off = in_sizes[25] / HEADS;

    cudaFuncSetAttribute(s_kernel,  cudaFuncAttributeMaxDynamicSharedMemorySize, S_SMEM);
    cudaFuncSetAttribute(mix_kernel, cudaFuncAttributeMaxDynamicSharedMemorySize, MIX_SMEM);

    fold_qkv_kernel<<<(OCQKV * DIM + 255) / 256, 256>>>(q_w, q_b, q_s, q_t,
                                                        k_w, k_b, k_s, k_t,
                                                        v_w, v_b, v_s, v_t);
    fold_proj_kernel<<<(DIM * DH + 255) / 256, 256>>>(proj_w, proj_b, proj_s, proj_t);
    fold_vl_kernel<<<(DH * 9 + 255) / 256, 256>>>(vl_w, vl_b, vl_s, vl_t);
    bias_expand_kernel<<<(HEADS * NPIX * NPIX + 255) / 256, 256>>>(bias_seg, bias_idx, n_off);

    gemm_mma<0><<<dim3(BATCH, OCQKV / 128), 512>>>(x, nullptr);

    vloc_kernel<<<BATCH * DH, 224>>>();

    s_kernel<<<dim3(BATCH, HEADS), 512, S_SMEM>>>();
    mix_kernel<<<dim3(BATCH, 14), 512, MIX_SMEM>>>(th1_w, th1_b, th2_w, th2_b);
    av_kernel<<<dim3(BATCH, HEADS), 512>>>();

    gemm_mma<1><<<dim3(BATCH, DIM / 128), 512>>>(nullptr, out);
}

// round 4
// speedup vs baseline: 1.0027x; 1.0027x over previous
#include <cuda_runtime.h>
#include <cstdint>

// ---------------- problem constants ----------------
#define BATCH   128
#define DIM     384
#define RES     14
#define NPIX    196
#define HEADS   8
#define KD      32
#define DV      128
#define DH      1024
#define OCQKV   1536
#define SCALE_ATTN 0.17677669529663687f
#define NPAD    208
#define QT      16
#define QTILES  13
#define SP      212              // S row stride (conflict-free: 212 mod 32 = 20)
#define VSTR    137              // staged-V row stride (conflict-free)

// ---------------- device scratch ----------------
__device__ float g_qkv [(size_t)BATCH * OCQKV * NPIX];
__device__ float g_vloc[(size_t)BATCH * DH * NPIX];
__device__ float g_xout[(size_t)BATCH * DH * NPIX];
__device__ float g_wqkv[OCQKV * DIM];
__device__ float g_bqkv[OCQKV];
__device__ float g_wproj[DIM * DH];
__device__ float g_bproj[DIM];
__device__ float g_wvl[DH * 9];
__device__ float g_bvl[DH];
__device__ float g_bias[HEADS * NPIX * NPIX];

// ---------------- tf32 helpers ----------------
__device__ __forceinline__ uint32_t f2tf(float f) {
    uint32_t u; asm("cvt.rna.tf32.f32 %0, %1;" : "=r"(u) : "f"(f)); return u;
}
__device__ __forceinline__ void mma8(float* c, uint32_t a0, uint32_t a1, uint32_t a2, uint32_t a3,
                                     uint32_t b0, uint32_t b1) {
    asm volatile(
        "mma.sync.aligned.m16n8k8.row.col.f32.tf32.tf32.f32 "
        "{%0,%1,%2,%3},{%4,%5,%6,%7},{%8,%9},{%0,%1,%2,%3};"
        : "+f"(c[0]), "+f"(c[1]), "+f"(c[2]), "+f"(c[3])
        : "r"(a0), "r"(a1), "r"(a2), "r"(a3), "r"(b0), "r"(b1));
}

// ---------------- BN folding ----------------
__global__ void fold_qkv_kernel(
    const float* __restrict__ q_w, const float* __restrict__ q_b,
    const float* __restrict__ q_s, const float* __restrict__ q_t,
    const float* __restrict__ k_w, const float* __restrict__ k_b,
    const float* __restrict__ k_s, const float* __restrict__ k_t,
    const float* __restrict__ v_w, const float* __restrict__ v_b,
    const float* __restrict__ v_s, const float* __restrict__ v_t)
{
    int idx = blockIdx.x * blockDim.x + threadIdx.x;
    if (idx >= OCQKV * DIM) return;
    int oc = idx / DIM, c = idx - oc * DIM;
    float w, s;
    if (oc < 256) {
        w = q_w[oc * DIM + c]; s = q_s[oc] * SCALE_ATTN;
        if (c == 0) g_bqkv[oc] = (q_b[oc] * q_s[oc] + q_t[oc]) * SCALE_ATTN;
    } else if (oc < 512) {
        int o = oc - 256;
        w = k_w[o * DIM + c]; s = k_s[o];
        if (c == 0) g_bqkv[oc] = k_b[o] * k_s[o] + k_t[o];
    } else {
        int o = oc - 512;
        w = v_w[o * DIM + c]; s = v_s[o];
        if (c == 0) g_bqkv[oc] = v_b[o] * v_s[o] + v_t[o];
    }
    g_wqkv[idx] = w * s;
}

__global__ void fold_proj_kernel(
    const float* __restrict__ p_w, const float* __restrict__ p_b,
    const float* __restrict__ p_s, const float* __restrict__ p_t)
{
    int idx = blockIdx.x * blockDim.x + threadIdx.x;
    if (idx >= DIM * DH) return;
    int oc = idx / DH;
    g_wproj[idx] = p_w[idx] * p_s[oc];
    if ((idx - oc * DH) == 0) g_bproj[oc] = p_b[oc] * p_s[oc] + p_t[oc];
}

__global__ void fold_vl_kernel(
    const float* __restrict__ vl_w, const float* __restrict__ vl_b,
    const float* __restrict__ vl_s, const float* __restrict__ vl_t)
{
    int idx = blockIdx.x * blockDim.x + threadIdx.x;
    if (idx >= DH * 9) return;
    int ch = idx / 9;
    g_wvl[idx] = vl_w[idx] * vl_s[ch];
    if (idx == ch * 9) g_bvl[ch] = vl_b[ch] * vl_s[ch] + vl_t[ch];
}

__global__ void bias_expand_kernel(const float* __restrict__ bias_seg,
                                   const int* __restrict__ bias_idxs, int n_off)
{
    int e = blockIdx.x * blockDim.x + threadIdx.x;
    if (e >= HEADS * NPIX * NPIX) return;
    int h = e / (NPIX * NPIX), nm = e - h * (NPIX * NPIX);
    g_bias[e] = bias_seg[h * n_off + bias_idxs[nm]];
}

// ---------------- tf32 mma GEMM: Y[b][oc][n] = W @ X + bias ----------------
// GRID: x = oc-block, y = batch  (same-batch CTAs adjacent -> X stays in L2)
#define BKG 32
template<int MODE>
__global__ __launch_bounds__(512, 1)
void gemm_mma(const float* __restrict__ Xin, float* __restrict__ Yout)
{
    const int K = (MODE == 0) ? DIM : DH;
    const float* __restrict__ W  = (MODE == 0) ? g_wqkv : g_wproj;
    const float* __restrict__ Bv = (MODE == 0) ? g_bqkv : g_bproj;
    const int b = blockIdx.y, oc0 = blockIdx.x * 128;
    const float* Xb = ((MODE == 0) ? Xin : g_xout) + (size_t)b * K * NPIX;
    float*       Yb = ((MODE == 0) ? g_qkv : Yout) + (size_t)b * ((MODE == 0) ? OCQKV : DIM) * NPIX;

    __shared__ uint32_t sW[BKG][129];
    __shared__ uint32_t sX[BKG][216];

    const int tid = threadIdx.x, lane = tid & 31, w = tid >> 5;
    const int ocg = w >> 1, half = w & 1, g = lane >> 2, q = lane & 3;
    const int ob = ocg * 16;

    float c[13][4];
    #pragma unroll
    for (int t = 0; t < 13; ++t) { c[t][0] = c[t][1] = c[t][2] = c[t][3] = 0.f; }

    for (int k0 = 0; k0 < K; k0 += BKG) {
        for (int e = tid; e < 128 * BKG; e += 512) {
            int oc = e >> 5, kk = e & 31;
            sW[kk][oc] = f2tf(W[(size_t)(oc0 + oc) * K + k0 + kk]);
        }
        for (int e = tid; e < BKG * NPAD; e += 512) {
            int kk = e / NPAD, n = e - kk * NPAD;
            sX[kk][n] = (n < NPIX) ? f2tf(Xb[(size_t)(k0 + kk) * NPIX + n]) : 0u;
        }
        __syncthreads();
        #pragma unroll
        for (int kk = 0; kk < 4; ++kk) {
            int cb = kk * 8;
            uint32_t a0 = sW[cb + q][ob + g],     a1 = sW[cb + q][ob + g + 8];
            uint32_t a2 = sW[cb + q + 4][ob + g], a3 = sW[cb + q + 4][ob + g + 8];
            #pragma unroll
            for (int t = 0; t < 13; ++t) {
                int n = (half * 13 + t) * 8 + g;
                mma8(c[t], a0, a1, a2, a3, sX[cb + q][n], sX[cb + q + 4][n]);
            }
        }
        __syncthreads();
    }

    int r1 = oc0 + ob + g, r2 = r1 + 8;
    float bb1 = Bv[r1], bb2 = Bv[r2];
    #pragma unroll
    for (int t = 0; t < 13; ++t) {
        int n0 = (half * 13 + t) * 8 + 2 * q;
        if (n0 < NPIX) {
            *(float2*)(Yb + (size_t)r1 * NPIX + n0) = make_float2(c[t][0] + bb1, c[t][1] + bb1);
            *(float2*)(Yb + (size_t)r2 * NPIX + n0) = make_float2(c[t][2] + bb2, c[t][3] + bb2);
        }
    }
}

// ---------------- depthwise 3x3 local-V ----------------
__global__ __launch_bounds__(224)
void vloc_kernel()
{
    int blk = blockIdx.x;
    int b = blk >> 10, ch = blk & 1023;
    __shared__ float sp[NPIX];
    __shared__ float swv[9];
    int t = threadIdx.x;
    const float* src = g_qkv + (size_t)b * OCQKV * NPIX + (size_t)(512 + ch) * NPIX;
    if (t < NPIX) sp[t] = src[t];
    if (t < 9)  swv[t] = g_wvl[ch * 9 + t];
    __syncthreads();
    if (t < NPIX) {
        int i = t / RES, j = t - i * RES;
        float acc = g_bvl[ch];
        #pragma unroll
        for (int di = 0; di < 3; ++di) {
            int ii = i + di - 1;
            if (ii < 0 || ii >= RES) continue;
            #pragma unroll
            for (int dj = 0; dj < 3; ++dj) {
                int jj = j + dj - 1;
                if (jj < 0 || jj >= RES) continue;
                acc += sp[ii * RES + jj] * swv[di * 3 + dj];
            }
        }
        g_vloc[(size_t)b * DH * NPIX + (size_t)ch * NPIX + t] = acc;
    }
}

// ---------------- fused attention ----------------
// smem: sS [8][16][SP] (logits/probs, later out-tiles) + sV [2 buf][2 heads][32 m][VSTR]
#define ATTN_SMEM ((HEADS * QT * SP + 2 * 2 * 32 * VSTR) * 4)

// stage one 32-m chunk of V for a head pair into buffer `buf`
#define AV_STAGE(rnd, buf) do {                                                   \
    int hp_ = (rnd) / 7, ck_ = (rnd) % 7;                                         \
    if (hp_ < 4) {                                                                \
        int m0_ = ck_ * 32;                                                       \
        const float* Vb0_ = g_qkv + base + (size_t)(512 + hp_ * 2 * DV) * NPIX;   \
        for (int e = tid; e < 2 * 128 * 16; e += 512) {                           \
            int mi = e & 15, d = (e >> 4) & 127, hh = e >> 11;                    \
            int m = m0_ + 2 * mi;                                                 \
            const float* vp_ = Vb0_ + (size_t)(hh * DV + d) * NPIX;               \
            float2 v2_;                                                           \
            if (m + 1 < NPIX)      v2_ = *(const float2*)(vp_ + m);               \
            else if (m < NPIX)     v2_ = make_float2(vp_[m], 0.f);                \
            else                   v2_ = make_float2(0.f, 0.f);                   \
            uint32_t* dst_ = sV + ((buf) * 2 + hh) * (32 * VSTR) + d;             \
            dst_[(2 * mi) * VSTR]     = f2tf(v2_.x);                              \
            dst_[(2 * mi + 1) * VSTR] = f2tf(v2_.y);                              \
        }                                                                         \
    }                                                                             \
} while (0)

__global__ __launch_bounds__(512, 1)
void attn_mma(const float* __restrict__ th1_w, const float* __restrict__ th1_b,
              const float* __restrict__ th2_w, const float* __restrict__ th2_b)
{
    extern __shared__ float sS[];                       // [8][16][SP]
    uint32_t* sV = (uint32_t*)(sS + HEADS * QT * SP);   // [2][2][32][VSTR]
    __shared__ float sTh1[64], sTh1b[8], sTh2[64], sTh2b[8];

    const int tile = blockIdx.x, b = blockIdx.y;
    const int nq0 = tile * QT;
    const int tid = threadIdx.x, lane = tid & 31, w = tid >> 5;
    const int h = w >> 1, half = w & 1, g = lane >> 2, q = lane & 3;
    const size_t base = (size_t)b * OCQKV * NPIX;
    const size_t xob  = (size_t)b * DH * NPIX;

    if (tid < 64) { sTh1[tid] = th1_w[tid]; sTh2[tid] = th2_w[tid]; }
    if (tid < 8)  { sTh1b[tid] = th1_b[tid]; sTh2b[tid] = th2_b[tid]; }

    // ---- S = Q^T K + bias ----
    {
        const float* Qp = g_qkv + base + (size_t)(h * KD) * NPIX;
        const float* Kp = g_qkv + base + (size_t)(256 + h * KD) * NPIX;
        int ra = min(nq0 + g, NPIX - 1), rb = min(nq0 + g + 8, NPIX - 1);
        float c[13][4];
        #pragma unroll
        for (int t = 0; t < 13; ++t) { c[t][0] = c[t][1] = c[t][2] = c[t][3] = 0.f; }
        #pragma unroll
        for (int kk = 0; kk < 4; ++kk) {
            int cb = kk * 8;
            uint32_t a0 = f2tf(Qp[(cb + q) * NPIX + ra]);
            uint32_t a1 = f2tf(Qp[(cb + q) * NPIX + rb]);
            uint32_t a2 = f2tf(Qp[(cb + q + 4) * NPIX + ra]);
            uint32_t a3 = f2tf(Qp[(cb + q + 4) * NPIX + rb]);
            #pragma unroll
            for (int t = 0; t < 13; ++t) {
                int m = (half * 13 + t) * 8 + g;
                int mm = min(m, NPIX - 1);
                mma8(c[t], a0, a1, a2, a3,
                     f2tf(Kp[(cb + q) * NPIX + mm]), f2tf(Kp[(cb + q + 4) * NPIX + mm]));
            }
        }
        float* sh = sS + h * QT * SP;
        const float* bh = g_bias + h * NPIX * NPIX;
        #pragma unroll
        for (int t = 0; t < 13; ++t) {
            int m0 = (half * 13 + t) * 8 + 2 * q;
            int r1 = nq0 + g, r2 = nq0 + g + 8;
            float v0 = c[t][0], v1 = c[t][1], v2 = c[t][2], v3 = c[t][3];
            if (m0 < NPIX) {
                if (r1 < NPIX) { v0 += bh[r1 * NPIX + m0]; v1 += bh[r1 * NPIX + m0 + 1]; }
                if (r2 < NPIX) { v2 += bh[r2 * NPIX + m0]; v3 += bh[r2 * NPIX + m0 + 1]; }
            } else { v0 = v1 = v2 = v3 = 0.f; }
            sh[g * SP + m0]       = v0;  sh[g * SP + m0 + 1]       = v1;
            sh[(g + 8) * SP + m0] = v2;  sh[(g + 8) * SP + m0 + 1] = v3;
        }
    }
    __syncthreads();

    // ---- talking-heads mix #1 ----
    for (int e = tid; e < QT * NPIX; e += 512) {
        int r = e / NPIX, m = e - r * NPIX;
        float sv[8];
        #pragma unroll
        for (int i = 0; i < 8; ++i) sv[i] = sS[(i * QT + r) * SP + m];
        #pragma unroll
        for (int o = 0; o < 8; ++o) {
            float a = sTh1b[o];
            #pragma unroll
            for (int i = 0; i < 8; ++i) a += sTh1[o * 8 + i] * sv[i];
            sS[(o * QT + r) * SP + m] = a;
        }
    }
    __syncthreads();

    // ---- softmax: warp w -> head h, rows half*8..half*8+7 ----
    for (int rr = 0; rr < 8; ++rr) {
        float* p = sS + (h * QT + half * 8 + rr) * SP;
        float mx = -1e30f;
        for (int m = lane; m < NPIX; m += 32) mx = fmaxf(mx, p[m]);
        #pragma unroll
        for (int o = 16; o; o >>= 1) mx = fmaxf(mx, __shfl_xor_sync(~0u, mx, o));
        float s = 0.f;
        for (int m = lane; m < NPIX; m += 32) { float ev = __expf(p[m] - mx); p[m] = ev; s += ev; }
        #pragma unroll
        for (int o = 16; o; o >>= 1) s += __shfl_xor_sync(~0u, s, o);
        float inv = 1.f / s;
        for (int m = lane; m < NPIX; m += 32) p[m] *= inv;
    }
    __syncthreads();

    // ---- talking-heads mix #2 ----
    for (int e = tid; e < QT * NPIX; e += 512) {
        int r = e / NPIX, m = e - r * NPIX;
        float sv[8];
        #pragma unroll
        for (int i = 0; i < 8; ++i) sv[i] = sS[(i * QT + r) * SP + m];
        #pragma unroll
        for (int o = 0; o < 8; ++o) {
            float a = sTh2b[o];
            #pragma unroll
            for (int i = 0; i < 8; ++i) a += sTh2[o * 8 + i] * sv[i];
            sS[(o * QT + r) * SP + m] = a;
        }
    }
    __syncthreads();

    // ---- out = P @ V : smem-staged V, 2 heads concurrent, double-buffered ----
    // warp w: head-of-pair hl = w>>3, d-slice d0 = (w&7)*16
    {
        const int hl = w >> 3;
        const int d0 = (w & 7) * 16;
        float c2[2][4];
        #pragma unroll
        for (int t = 0; t < 2; ++t) c2[t][0] = c2[t][1] = c2[t][2] = c2[t][3] = 0.f;

        AV_STAGE(0, 0);
        for (int rnd = 0; rnd < 28; ++rnd) {
            __syncthreads();
            AV_STAGE(rnd + 1, (rnd + 1) & 1);
            {
                int hp = rnd / 7, ck = rnd % 7;
                int h2 = hp * 2 + hl;
                const float* sP = sS + h2 * QT * SP;
                const uint32_t* sVh = sV + ((rnd & 1) * 2 + hl) * (32 * VSTR);
                #pragma unroll
                for (int ks = 0; ks < 4; ++ks) {
                    int mb = ck * 32 + ks * 8;
                    uint32_t a0 = f2tf(sP[g * SP + mb + q]);
                    uint32_t a1 = f2tf(sP[(g + 8) * SP + mb + q]);
                    uint32_t a2 = f2tf(sP[g * SP + mb + q + 4]);
                    uint32_t a3 = f2tf(sP[(g + 8) * SP + mb + q + 4]);
                    const uint32_t* bq  = sVh + (ks * 8 + q) * VSTR;
                    const uint32_t* bq4 = sVh + (ks * 8 + q + 4) * VSTR;
                    mma8(c2[0], a0, a1, a2, a3, bq[d0 + g],     bq4[d0 + g]);
                    mma8(c2[1], a0, a1, a2, a3, bq[d0 + 8 + g], bq4[d0 + 8 + g]);
                }
            }
            if ((rnd % 7) == 6) {
                __syncthreads();   // all warps done reading this head-pair's P
                int h2 = (rnd / 7) * 2 + hl;
                float* so = sS + h2 * QT * SP;   // reuse as out tile [d*17 + r]
                #pragma unroll
                for (int t = 0; t < 2; ++t) {
                    int d = d0 + t * 8 + 2 * q;
                    so[d * 17 + g]           = c2[t][0];
                    so[(d + 1) * 17 + g]     = c2[t][1];
                    so[d * 17 + g + 8]       = c2[t][2];
                    so[(d + 1) * 17 + g + 8] = c2[t][3];
                    c2[t][0] = c2[t][1] = c2[t][2] = c2[t][3] = 0.f;
                }
            }
        }
    }
    __syncthreads();

    // ---- fused epilogue: + vloc, relu, coalesced store ----
    int rlim = min(QT, NPIX - nq0);
    for (int e = tid; e < HEADS * DV * QT; e += 512) {
        int h2 = e >> 11, rem = e & 2047, d = rem >> 4, r = rem & 15;
        if (r < rlim) {
            int ch = h2 * DV + d;
            size_t oi = xob + (size_t)ch * NPIX + nq0 + r;
            float val = sS[h2 * QT * SP + d * 17 + r] + g_vloc[oi];
            g_xout[oi] = fmaxf(val, 0.f);
        }
    }
}

// ---------------- host launch ----------------
extern "C" void kernel_launch(void* const* d_in, const int* in_sizes, int n_in,
                              void* d_out, int out_size)
{
    const float* x        = (const float*)d_in[0];
    const float* q_w      = (const float*)d_in[1];
    const float* q_b      = (const float*)d_in[2];
    const float* q_s      = (const float*)d_in[3];
    const float* q_t      = (const float*)d_in[4];
    const float* k_w      = (const float*)d_in[5];
    const float* k_b      = (const float*)d_in[6];
    const float* k_s      = (const float*)d_in[7];
    const float* k_t      = (const float*)d_in[8];
    const float* v_w      = (const float*)d_in[9];
    const float* v_b      = (const float*)d_in[10];
    const float* v_s      = (const float*)d_in[11];
    const float* v_t      = (const float*)d_in[12];
    const float* vl_w     = (const float*)d_in[13];
    const float* vl_b     = (const float*)d_in[14];
    const float* vl_s     = (const float*)d_in[15];
    const float* vl_t     = (const float*)d_in[16];
    const float* th1_w    = (const float*)d_in[17];
    const float* th1_b    = (const float*)d_in[18];
    const float* th2_w    = (const float*)d_in[19];
    const float* th2_b    = (const float*)d_in[20];
    const float* proj_w   = (const float*)d_in[21];
    const float* proj_b   = (const float*)d_in[22];
    const float* proj_s   = (const float*)d_in[23];
    const float* proj_t   = (const float*)d_in[24];
    const float* bias_seg = (const float*)d_in[25];
    const int*   bias_idx = (const int*)  d_in[26];
    float*       out      = (float*)d_out;

    const int n_off = in_sizes[25] / HEADS;

    cudaFuncSetAttribute(attn_mma, cudaFuncAttributeMaxDynamicSharedMemorySize, ATTN_SMEM);

    fold_qkv_kernel<<<(OCQKV * DIM + 255) / 256, 256>>>(q_w, q_b, q_s, q_t,
                                                        k_w, k_b, k_s, k_t,
                                                        v_w, v_b, v_s, v_t);
    fold_proj_kernel<<<(DIM * DH + 255) / 256, 256>>>(proj_w, proj_b, proj_s, proj_t);
    fold_vl_kernel<<<(DH * 9 + 255) / 256, 256>>>(vl_w, vl_b, vl_s, vl_t);
    bias_expand_kernel<<<(HEADS * NPIX * NPIX + 255) / 256, 256>>>(bias_seg, bias_idx, n_off);

    // grid: x = oc-block (fast), y = batch  -> same-batch CTAs adjacent
    gemm_mma<0><<<dim3(OCQKV / 128, BATCH), 512>>>(x, nullptr);

    vloc_kernel<<<BATCH * DH, 224>>>();

    attn_mma<<<dim3(QTILES, BATCH), 512, ATTN_SMEM>>>(th1_w, th1_b, th2_w, th2_b);

    gemm_mma<1><<<dim3(DIM / 128, BATCH), 512>>>(nullptr, out);
}

// round 5
// speedup vs baseline: 1.7215x; 1.7169x over previous
#include <cuda_runtime.h>
#include <cstdint>

// ---------------- problem constants ----------------
#define BATCH   128
#define DIM     384
#define RES     14
#define NPIX    196
#define HEADS   8
#define KD      32
#define DV      128
#define DH      1024
#define OCQKV   1536
#define SCALE_ATTN 0.17677669529663687f
#define NPAD    208
#define QT      16
#define QTILES  13
#define SP      208              // S row stride in attn smem (round-2 proven)

// ---------------- device scratch ----------------
__device__ float g_qkv [(size_t)BATCH * OCQKV * NPIX];
__device__ float g_vloc[(size_t)BATCH * DH * NPIX];
__device__ float g_xout[(size_t)BATCH * DH * NPIX];
__device__ float g_xtf [(size_t)BATCH * DIM * NPIX];   // tf32-rounded input x
__device__ float g_wqkv[OCQKV * DIM];
__device__ float g_bqkv[OCQKV];
__device__ float g_wproj[DIM * DH];
__device__ float g_bproj[DIM];
__device__ float g_wvl[DH * 9];
__device__ float g_bvl[DH];
__device__ float g_bias[HEADS * NPIX * NPIX];

// ---------------- tf32 helpers ----------------
__device__ __forceinline__ uint32_t f2tf(float f) {
    uint32_t u; asm("cvt.rna.tf32.f32 %0, %1;" : "=r"(u) : "f"(f)); return u;
}
__device__ __forceinline__ void mma8(float* c, uint32_t a0, uint32_t a1, uint32_t a2, uint32_t a3,
                                     uint32_t b0, uint32_t b1) {
    asm volatile(
        "mma.sync.aligned.m16n8k8.row.col.f32.tf32.tf32.f32 "
        "{%0,%1,%2,%3},{%4,%5,%6,%7},{%8,%9},{%0,%1,%2,%3};"
        : "+f"(c[0]), "+f"(c[1]), "+f"(c[2]), "+f"(c[3])
        : "r"(a0), "r"(a1), "r"(a2), "r"(a3), "r"(b0), "r"(b1));
}
__device__ __forceinline__ void cp16(uint32_t smem_dst, const void* gsrc) {
    asm volatile("cp.async.cg.shared.global [%0], [%1], 16;" :: "r"(smem_dst), "l"(gsrc));
}
#define CP_COMMIT()  asm volatile("cp.async.commit_group;")
#define CP_WAIT(n)   asm volatile("cp.async.wait_group %0;" :: "n"(n))

// ---------------- pre-round x to tf32 ----------------
__global__ void x_round_kernel(const float* __restrict__ x)
{
    int i = blockIdx.x * blockDim.x + threadIdx.x;
    int tot = BATCH * DIM * NPIX / 4;
    if (i >= tot) return;
    float4 v = ((const float4*)x)[i];
    v.x = __uint_as_float(f2tf(v.x));
    v.y = __uint_as_float(f2tf(v.y));
    v.z = __uint_as_float(f2tf(v.z));
    v.w = __uint_as_float(f2tf(v.w));
    ((float4*)g_xtf)[i] = v;
}

// ---------------- BN folding (weights stored tf32-rounded) ----------------
__global__ void fold_qkv_kernel(
    const float* __restrict__ q_w, const float* __restrict__ q_b,
    const float* __restrict__ q_s, const float* __restrict__ q_t,
    const float* __restrict__ k_w, const float* __restrict__ k_b,
    const float* __restrict__ k_s, const float* __restrict__ k_t,
    const float* __restrict__ v_w, const float* __restrict__ v_b,
    const float* __restrict__ v_s, const float* __restrict__ v_t)
{
    int idx = blockIdx.x * blockDim.x + threadIdx.x;
    if (idx >= OCQKV * DIM) return;
    int oc = idx / DIM, c = idx - oc * DIM;
    float w, s;
    if (oc < 256) {
        w = q_w[oc * DIM + c]; s = q_s[oc] * SCALE_ATTN;
        if (c == 0) g_bqkv[oc] = (q_b[oc] * q_s[oc] + q_t[oc]) * SCALE_ATTN;
    } else if (oc < 512) {
        int o = oc - 256;
        w = k_w[o * DIM + c]; s = k_s[o];
        if (c == 0) g_bqkv[oc] = k_b[o] * k_s[o] + k_t[o];
    } else {
        int o = oc - 512;
        w = v_w[o * DIM + c]; s = v_s[o];
        if (c == 0) g_bqkv[oc] = v_b[o] * v_s[o] + v_t[o];
    }
    g_wqkv[idx] = __uint_as_float(f2tf(w * s));
}

__global__ void fold_proj_kernel(
    const float* __restrict__ p_w, const float* __restrict__ p_b,
    const float* __restrict__ p_s, const float* __restrict__ p_t)
{
    int idx = blockIdx.x * blockDim.x + threadIdx.x;
    if (idx >= DIM * DH) return;
    int oc = idx / DH;
    g_wproj[idx] = __uint_as_float(f2tf(p_w[idx] * p_s[oc]));
    if ((idx - oc * DH) == 0) g_bproj[oc] = p_b[oc] * p_s[oc] + p_t[oc];
}

__global__ void fold_vl_kernel(
    const float* __restrict__ vl_w, const float* __restrict__ vl_b,
    const float* __restrict__ vl_s, const float* __restrict__ vl_t)
{
    int idx = blockIdx.x * blockDim.x + threadIdx.x;
    if (idx >= DH * 9) return;
    int ch = idx / 9;
    g_wvl[idx] = vl_w[idx] * vl_s[ch];
    if (idx == ch * 9) g_bvl[ch] = vl_b[ch] * vl_s[ch] + vl_t[ch];
}

__global__ void bias_expand_kernel(const float* __restrict__ bias_seg,
                                   const int* __restrict__ bias_idxs, int n_off)
{
    int e = blockIdx.x * blockDim.x + threadIdx.x;
    if (e >= HEADS * NPIX * NPIX) return;
    int h = e / (NPIX * NPIX), nm = e - h * (NPIX * NPIX);
    g_bias[e] = bias_seg[h * n_off + bias_idxs[nm]];
}

// ---------------- cp.async double-buffered tf32 GEMM ----------------
// Y[b][oc][n] = W @ X + bias. CTA: 128 oc x 208 n. 512 thr = 16 warps.
// smem (dynamic): sW [2][128][36]  (raw tf32-rounded floats, [oc][k] layout)
//                 sX [2][32][216]
#define WSTR 36
#define XSTR 216
#define GEMM_SMEM ((2 * 128 * WSTR + 2 * 32 * XSTR) * 4)

template<int MODE>
__global__ __launch_bounds__(512, 1)
void gemm_mma(float* __restrict__ Yout)
{
    const int K = (MODE == 0) ? DIM : DH;
    const float* __restrict__ W  = (MODE == 0) ? g_wqkv : g_wproj;
    const float* __restrict__ Bv = (MODE == 0) ? g_bqkv : g_bproj;
    const int b = blockIdx.x, oc0 = blockIdx.y * 128;
    const float* Xb = ((MODE == 0) ? g_xtf : g_xout) + (size_t)b * K * NPIX;
    float*       Yb = ((MODE == 0) ? g_qkv : Yout) + (size_t)b * ((MODE == 0) ? OCQKV : DIM) * NPIX;

    extern __shared__ uint32_t smem[];
    uint32_t* sW = smem;                       // [buf][oc][WSTR]
    uint32_t* sX = smem + 2 * 128 * WSTR;      // [buf][kk][XSTR]

    const int tid = threadIdx.x, lane = tid & 31, w = tid >> 5;
    const int ocg = w >> 1, half = w & 1, g = lane >> 2, q = lane & 3;
    const int ob = ocg * 16;

    // zero X pad columns (196..215) for both buffers — never overwritten
    for (int e = tid; e < 2 * 32 * 20; e += 512) {
        int buf = e / (32 * 20), rem = e % (32 * 20);
        int kk = rem / 20, n = 196 + rem % 20;
        sX[(buf * 32 + kk) * XSTR + n] = 0u;
    }

    const int NIT = K / 32;
    uint32_t sW_base = (uint32_t)__cvta_generic_to_shared(sW);
    uint32_t sX_base = (uint32_t)__cvta_generic_to_shared(sX);

    // stage a k-tile into buffer `buf`
    auto stage = [&](int it, int buf) {
        int k0 = it * 32;
        // W tile: 128 rows x 32 k = 1024 16B chunks
        for (int e = tid; e < 1024; e += 512) {
            int oc = e >> 3, c = e & 7;
            cp16(sW_base + ((buf * 128 + oc) * WSTR + c * 4) * 4,
                 W + (size_t)(oc0 + oc) * K + k0 + c * 4);
        }
        // X tile: 32 rows x 196 = 1568 chunks (rows 784B, 16B-aligned)
        for (int e = tid; e < 1568; e += 512) {
            int kk = e / 49, c = e % 49;
            cp16(sX_base + ((buf * 32 + kk) * XSTR + c * 4) * 4,
                 Xb + (size_t)(k0 + kk) * NPIX + c * 4);
        }
        CP_COMMIT();
    };

    float c[13][4];
    #pragma unroll
    for (int t = 0; t < 13; ++t) { c[t][0] = c[t][1] = c[t][2] = c[t][3] = 0.f; }

    stage(0, 0);
    int buf = 0;
    for (int it = 0; it < NIT; ++it) {
        if (it + 1 < NIT) { stage(it + 1, buf ^ 1); CP_WAIT(1); }
        else             { CP_WAIT(0); }
        __syncthreads();
        const uint32_t* cW = sW + buf * 128 * WSTR;
        const uint32_t* cX = sX + buf * 32 * XSTR;
        #pragma unroll
        for (int kk = 0; kk < 4; ++kk) {
            int cb = kk * 8;
            uint32_t a0 = cW[(ob + g) * WSTR + cb + q];
            uint32_t a1 = cW[(ob + g + 8) * WSTR + cb + q];
            uint32_t a2 = cW[(ob + g) * WSTR + cb + q + 4];
            uint32_t a3 = cW[(ob + g + 8) * WSTR + cb + q + 4];
            #pragma unroll
            for (int t = 0; t < 13; ++t) {
                int n = (half * 13 + t) * 8 + g;
                mma8(c[t], a0, a1, a2, a3, cX[(cb + q) * XSTR + n], cX[(cb + q + 4) * XSTR + n]);
            }
        }
        __syncthreads();
        buf ^= 1;
    }

    int r1 = oc0 + ob + g, r2 = r1 + 8;
    float bb1 = Bv[r1], bb2 = Bv[r2];
    #pragma unroll
    for (int t = 0; t < 13; ++t) {
        int n0 = (half * 13 + t) * 8 + 2 * q;
        if (n0 < NPIX) {
            *(float2*)(Yb + (size_t)r1 * NPIX + n0) = make_float2(c[t][0] + bb1, c[t][1] + bb1);
            *(float2*)(Yb + (size_t)r2 * NPIX + n0) = make_float2(c[t][2] + bb2, c[t][3] + bb2);
        }
    }
}

// ---------------- depthwise 3x3 local-V ----------------
__global__ __launch_bounds__(224)
void vloc_kernel()
{
    int blk = blockIdx.x;
    int b = blk >> 10, ch = blk & 1023;
    __shared__ float sp[NPIX];
    __shared__ float swv[9];
    int t = threadIdx.x;
    const float* src = g_qkv + (size_t)b * OCQKV * NPIX + (size_t)(512 + ch) * NPIX;
    if (t < NPIX) sp[t] = src[t];
    if (t < 9)  swv[t] = g_wvl[ch * 9 + t];
    __syncthreads();
    if (t < NPIX) {
        int i = t / RES, j = t - i * RES;
        float acc = g_bvl[ch];
        #pragma unroll
        for (int di = 0; di < 3; ++di) {
            int ii = i + di - 1;
            if (ii < 0 || ii >= RES) continue;
            #pragma unroll
            for (int dj = 0; dj < 3; ++dj) {
                int jj = j + dj - 1;
                if (jj < 0 || jj >= RES) continue;
                acc += sp[ii * RES + jj] * swv[di * 3 + dj];
            }
        }
        g_vloc[(size_t)b * DH * NPIX + (size_t)ch * NPIX + t] = acc;
    }
}

// ---------------- fused attention (round-2 proven version) ----------------
#define ATTN_SMEM (HEADS * QT * SP * 4)

__global__ __launch_bounds__(512, 1)
void attn_mma(const float* __restrict__ th1_w, const float* __restrict__ th1_b,
              const float* __restrict__ th2_w, const float* __restrict__ th2_b)
{
    extern __shared__ float sS[];            // [8][16][SP]
    __shared__ float sTh1[64], sTh1b[8], sTh2[64], sTh2b[8];

    const int tile = blockIdx.x, b = blockIdx.y;
    const int nq0 = tile * QT;
    const int tid = threadIdx.x, lane = tid & 31, w = tid >> 5;
    const int h = w >> 1, half = w & 1, g = lane >> 2, q = lane & 3;
    const size_t base = (size_t)b * OCQKV * NPIX;
    const size_t xob  = (size_t)b * DH * NPIX;

    if (tid < 64) { sTh1[tid] = th1_w[tid]; sTh2[tid] = th2_w[tid]; }
    if (tid < 8)  { sTh1b[tid] = th1_b[tid]; sTh2b[tid] = th2_b[tid]; }

    // ---- S = Q^T K + bias ----
    {
        const float* Qp = g_qkv + base + (size_t)(h * KD) * NPIX;
        const float* Kp = g_qkv + base + (size_t)(256 + h * KD) * NPIX;
        int ra = min(nq0 + g, NPIX - 1), rb = min(nq0 + g + 8, NPIX - 1);
        float c[13][4];
        #pragma unroll
        for (int t = 0; t < 13; ++t) { c[t][0] = c[t][1] = c[t][2] = c[t][3] = 0.f; }
        #pragma unroll
        for (int kk = 0; kk < 4; ++kk) {
            int cb = kk * 8;
            uint32_t a0 = f2tf(Qp[(cb + q) * NPIX + ra]);
            uint32_t a1 = f2tf(Qp[(cb + q) * NPIX + rb]);
            uint32_t a2 = f2tf(Qp[(cb + q + 4) * NPIX + ra]);
            uint32_t a3 = f2tf(Qp[(cb + q + 4) * NPIX + rb]);
            #pragma unroll
            for (int t = 0; t < 13; ++t) {
                int m = (half * 13 + t) * 8 + g;
                int mm = min(m, NPIX - 1);
                mma8(c[t], a0, a1, a2, a3,
                     f2tf(Kp[(cb + q) * NPIX + mm]), f2tf(Kp[(cb + q + 4) * NPIX + mm]));
            }
        }
        float* sh = sS + h * QT * SP;
        const float* bh = g_bias + h * NPIX * NPIX;
        #pragma unroll
        for (int t = 0; t < 13; ++t) {
            int m0 = (half * 13 + t) * 8 + 2 * q;
            int r1 = nq0 + g, r2 = nq0 + g + 8;
            float v0 = c[t][0], v1 = c[t][1], v2 = c[t][2], v3 = c[t][3];
            if (m0 < NPIX) {
                if (r1 < NPIX) { v0 += bh[r1 * NPIX + m0]; v1 += bh[r1 * NPIX + m0 + 1]; }
                if (r2 < NPIX) { v2 += bh[r2 * NPIX + m0]; v3 += bh[r2 * NPIX + m0 + 1]; }
            } else { v0 = v1 = v2 = v3 = 0.f; }
            sh[g * SP + m0]       = v0;  sh[g * SP + m0 + 1]       = v1;
            sh[(g + 8) * SP + m0] = v2;  sh[(g + 8) * SP + m0 + 1] = v3;
        }
    }
    __syncthreads();

    // ---- talking-heads mix #1 ----
    for (int e = tid; e < QT * NPIX; e += 512) {
        int r = e / NPIX, m = e - r * NPIX;
        float sv[8];
        #pragma unroll
        for (int i = 0; i < 8; ++i) sv[i] = sS[(i * QT + r) * SP + m];
        #pragma unroll
        for (int o = 0; o < 8; ++o) {
            float a = sTh1b[o];
            #pragma unroll
            for (int i = 0; i < 8; ++i) a += sTh1[o * 8 + i] * sv[i];
            sS[(o * QT + r) * SP + m] = a;
        }
    }
    __syncthreads();

    // ---- softmax ----
    for (int rr = 0; rr < 8; ++rr) {
        float* p = sS + (h * QT + half * 8 + rr) * SP;
        float mx = -1e30f;
        for (int m = lane; m < NPIX; m += 32) mx = fmaxf(mx, p[m]);
        #pragma unroll
        for (int o = 16; o; o >>= 1) mx = fmaxf(mx, __shfl_xor_sync(~0u, mx, o));
        float s = 0.f;
        for (int m = lane; m < NPIX; m += 32) { float ev = __expf(p[m] - mx); p[m] = ev; s += ev; }
        #pragma unroll
        for (int o = 16; o; o >>= 1) s += __shfl_xor_sync(~0u, s, o);
        float inv = 1.f / s;
        for (int m = lane; m < NPIX; m += 32) p[m] *= inv;
    }
    __syncthreads();

    // ---- talking-heads mix #2 ----
    for (int e = tid; e < QT * NPIX; e += 512) {
        int r = e / NPIX, m = e - r * NPIX;
        float sv[8];
        #pragma unroll
        for (int i = 0; i < 8; ++i) sv[i] = sS[(i * QT + r) * SP + m];
        #pragma unroll
        for (int o = 0; o < 8; ++o) {
            float a = sTh2b[o];
            #pragma unroll
            for (int i = 0; i < 8; ++i) a += sTh2[o * 8 + i] * sv[i];
            sS[(o * QT + r) * SP + m] = a;
        }
    }
    __syncthreads();

    // ---- out = P @ V^T (direct V gathers; L2-resident) ----
    {
        const float* Vp = g_qkv + base + (size_t)(512 + h * DV) * NPIX;
        const float* sP = sS + h * QT * SP;
        float c[8][4];
        #pragma unroll
        for (int t = 0; t < 8; ++t) { c[t][0] = c[t][1] = c[t][2] = c[t][3] = 0.f; }
        #pragma unroll
        for (int kk = 0; kk < 26; ++kk) {
            int mb = kk * 8;
            uint32_t a0 = f2tf(sP[g * SP + mb + q]);
            uint32_t a1 = f2tf(sP[(g + 8) * SP + mb + q]);
            uint32_t a2 = f2tf(sP[g * SP + mb + q + 4]);
            uint32_t a3 = f2tf(sP[(g + 8) * SP + mb + q + 4]);
            int m1 = min(mb + q, NPIX - 1), m2 = min(mb + q + 4, NPIX - 1);
            #pragma unroll
            for (int t = 0; t < 8; ++t) {
                int d = (half * 8 + t) * 8 + g;
                mma8(c[t], a0, a1, a2, a3,
                     f2tf(Vp[d * NPIX + m1]), f2tf(Vp[d * NPIX + m2]));
            }
        }
        __syncthreads();
        float* so = sS + h * QT * SP;   // reuse as out tile [d*17 + r]
        #pragma unroll
        for (int t = 0; t < 8; ++t) {
            int d = (half * 8 + t) * 8 + 2 * q;
            so[d * 17 + g]           = c[t][0];
            so[(d + 1) * 17 + g]     = c[t][1];
            so[d * 17 + g + 8]       = c[t][2];
            so[(d + 1) * 17 + g + 8] = c[t][3];
        }
    }
    __syncthreads();

    // ---- fused epilogue: + vloc, relu, tf32-round, coalesced store ----
    int rlim = min(QT, NPIX - nq0);
    for (int e = tid; e < HEADS * DV * QT; e += 512) {
        int h2 = e >> 11, rem = e & 2047, d = rem >> 4, r = rem & 15;
        if (r < rlim) {
            int ch = h2 * DV + d;
            size_t oi = xob + (size_t)ch * NPIX + nq0 + r;
            float val = sS[h2 * QT * SP + d * 17 + r] + g_vloc[oi];
            g_xout[oi] = __uint_as_float(f2tf(fmaxf(val, 0.f)));
        }
    }
}

// ---------------- host launch ----------------
extern "C" void kernel_launch(void* const* d_in, const int* in_sizes, int n_in,
                              void* d_out, int out_size)
{
    const float* x        = (const float*)d_in[0];
    const float* q_w      = (const float*)d_in[1];
    const float* q_b      = (const float*)d_in[2];
    const float* q_s      = (const float*)d_in[3];
    const float* q_t      = (const float*)d_in[4];
    const float* k_w      = (const float*)d_in[5];
    const float* k_b      = (const float*)d_in[6];
    const float* k_s      = (const float*)d_in[7];
    const float* k_t      = (const float*)d_in[8];
    const float* v_w      = (const float*)d_in[9];
    const float* v_b      = (const float*)d_in[10];
    const float* v_s      = (const float*)d_in[11];
    const float* v_t      = (const float*)d_in[12];
    const float* vl_w     = (const float*)d_in[13];
    const float* vl_b     = (const float*)d_in[14];
    const float* vl_s     = (const float*)d_in[15];
    const float* vl_t     = (const float*)d_in[16];
    const float* th1_w    = (const float*)d_in[17];
    const float* th1_b    = (const float*)d_in[18];
    const float* th2_w    = (const float*)d_in[19];
    const float* th2_b    = (const float*)d_in[20];
    const float* proj_w   = (const float*)d_in[21];
    const float* proj_b   = (const float*)d_in[22];
    const float* proj_s   = (const float*)d_in[23];
    const float* proj_t   = (const float*)d_in[24];
    const float* bias_seg = (const float*)d_in[25];
    const int*   bias_idx = (const int*)  d_in[26];
    float*       out      = (float*)d_out;

    const int n_off = in_sizes[25] / HEADS;

    cudaFuncSetAttribute(attn_mma, cudaFuncAttributeMaxDynamicSharedMemorySize, ATTN_SMEM);
    cudaFuncSetAttribute(gemm_mma<0>, cudaFuncAttributeMaxDynamicSharedMemorySize, GEMM_SMEM);
    cudaFuncSetAttribute(gemm_mma<1>, cudaFuncAttributeMaxDynamicSharedMemorySize, GEMM_SMEM);

    // launch order arranged so gemm_mma<0> is the 4th launch (profiled slot)
    x_round_kernel<<<(BATCH * DIM * NPIX / 4 + 255) / 256, 256>>>(x);
    fold_qkv_kernel<<<(OCQKV * DIM + 255) / 256, 256>>>(q_w, q_b, q_s, q_t,
                                                        k_w, k_b, k_s, k_t,
                                                        v_w, v_b, v_s, v_t);
    fold_proj_kernel<<<(DIM * DH + 255) / 256, 256>>>(proj_w, proj_b, proj_s, proj_t);

    gemm_mma<0><<<dim3(BATCH, OCQKV / 128), 512, GEMM_SMEM>>>(nullptr);   // 4th launch

    fold_vl_kernel<<<(DH * 9 + 255) / 256, 256>>>(vl_w, vl_b, vl_s, vl_t);
    bias_expand_kernel<<<(HEADS * NPIX * NPIX + 255) / 256, 256>>>(bias_seg, bias_idx, n_off);

    vloc_kernel<<<BATCH * DH, 224>>>();

    attn_mma<<<dim3(QTILES, BATCH), 512, ATTN_SMEM>>>(th1_w, th1_b, th2_w, th2_b);

    gemm_mma<1><<<dim3(BATCH, DIM / 128), 512, GEMM_SMEM>>>(out);
}

// round 8
// speedup vs baseline: 2.4168x; 1.4038x over previous
#include <cuda_runtime.h>
#include <cuda_fp16.h>
#include <cstdint>

// ---------------- problem constants ----------------
#define BATCH   128
#define DIM     384
#define RES     14
#define NPIX    196
#define HEADS   8
#define KD      32
#define DV      128
#define DH      1024
#define OCQKV   1536
#define SCALE_ATTN 0.17677669529663687f
#define QT      16
#define QTILES  13
#define SP      208        // S row stride (floats) in attn smem
#define PST     105        // P half2 row stride (words) in attn smem

// ---------------- device scratch (16B-aligned: cp.async / vector access) ----------------
__device__ __align__(16) __half   g_wqkv [OCQKV * DIM];
__device__ float    g_bqkv [OCQKV];
__device__ __align__(16) __half   g_wproj[DIM * DH];
__device__ float    g_bproj[DIM];
__device__ float    g_wvl  [DH * 9];
__device__ float    g_bvl  [DH];
__device__ float    g_bias [HEADS * NPIX * NPIX];
__device__ __align__(16) uint32_t g_xp32 [(size_t)BATCH * 192 * NPIX];     // x half2-pairs [b][cpair][n]
__device__ __align__(16) uint32_t g_qp32 [(size_t)BATCH * 128 * 208];      // Q [b][cpair][n(208)]
__device__ __align__(16) uint32_t g_kp32 [(size_t)BATCH * 128 * 208];      // K [b][cpair][n(208)]
__device__ __align__(16) uint32_t g_vp32 [(size_t)BATCH * 104 * DH];       // V [b][mpair(104)][ch]
__device__ __align__(16) float    g_vf   [(size_t)BATCH * DH * NPIX];      // V float (vloc input)
__device__ __align__(16) float    g_vlp  [(size_t)BATCH * 512 * NPIX * 2]; // vloc paired
__device__ __align__(16) uint32_t g_xop32[(size_t)BATCH * 512 * NPIX];     // xout half2 [b][chpair][n]

// ---------------- helpers ----------------
__device__ __forceinline__ uint32_t packh2(float lo, float hi) {
    __half2 h = __floats2half2_rn(lo, hi);
    return *(uint32_t*)&h;
}
__device__ __forceinline__ void mma16(float* c, uint32_t a0, uint32_t a1, uint32_t a2, uint32_t a3,
                                      uint32_t b0, uint32_t b1) {
    asm volatile(
        "mma.sync.aligned.m16n8k16.row.col.f32.f16.f16.f32 "
        "{%0,%1,%2,%3},{%4,%5,%6,%7},{%8,%9},{%0,%1,%2,%3};"
        : "+f"(c[0]), "+f"(c[1]), "+f"(c[2]), "+f"(c[3])
        : "r"(a0), "r"(a1), "r"(a2), "r"(a3), "r"(b0), "r"(b1));
}
__device__ __forceinline__ void cp16(uint32_t smem_dst, const void* gsrc) {
    asm volatile("cp.async.cg.shared.global [%0], [%1], 16;" :: "r"(smem_dst), "l"(gsrc));
}
#define CP_COMMIT()  asm volatile("cp.async.commit_group;")
#define CP_WAIT(n)   asm volatile("cp.async.wait_group %0;" :: "n"(n))

#define WST 20
#define XST 212

// stage one 32-k tile of W (128 rows) + X (16 pair-rows) into buffer `buf`
__device__ __forceinline__ void gemm_stage(const __half* W, int ldw, const uint32_t* Xp,
                                           int oc0, int it, int buf,
                                           uint32_t sWb, uint32_t sXb, int tid)
{
    int k0 = it * 32;
    {
        int oc = tid >> 2, cc = tid & 3;   // tid < 512 covers 128x4 chunks exactly
        cp16(sWb + (((buf * 128) + oc) * WST + cc * 4) * 4,
             W + (size_t)(oc0 + oc) * ldw + k0 + cc * 8);
    }
    for (int e = tid; e < 784; e += 512) {
        int pr = e / 49, cc = e % 49;
        cp16(sXb + ((buf * 16 + pr) * XST + cc * 4) * 4,
             Xp + (size_t)(it * 16 + pr) * NPIX + cc * 4);
    }
    CP_COMMIT();
}

// ---------------- prep kernels ----------------
__global__ void x_prep_kernel(const float* __restrict__ x)
{
    int idx = blockIdx.x * blockDim.x + threadIdx.x;
    if (idx >= BATCH * 192 * NPIX) return;
    int n = idx % NPIX, cp = (idx / NPIX) % 192, b = idx / (NPIX * 192);
    const float* xr = x + ((size_t)b * DIM + 2 * cp) * NPIX + n;
    g_xp32[idx] = packh2(xr[0], xr[NPIX]);
}

__global__ void pad_zero_kernel()
{
    int idx = blockIdx.x * blockDim.x + threadIdx.x;
    if (idx >= BATCH * 9216) return;
    int b = idx / 9216, i = idx % 9216;
    if (i < 1536) {
        int cp = i / 12, ni = i % 12;
        g_qp32[((size_t)b * 128 + cp) * 208 + 196 + ni] = 0u;
    } else if (i < 3072) {
        int r = i - 1536, cp = r / 12, ni = r % 12;
        g_kp32[((size_t)b * 128 + cp) * 208 + 196 + ni] = 0u;
    } else {
        int r = i - 3072;
        int mp = 98 + r / DH, d = r % DH;
        g_vp32[(size_t)b * 104 * DH + (size_t)mp * DH + d] = 0u;
    }
}

// ---------------- BN folding ----------------
__global__ void fold_qkv_kernel(
    const float* __restrict__ q_w, const float* __restrict__ q_b,
    const float* __restrict__ q_s, const float* __restrict__ q_t,
    const float* __restrict__ k_w, const float* __restrict__ k_b,
    const float* __restrict__ k_s, const float* __restrict__ k_t,
    const float* __restrict__ v_w, const float* __restrict__ v_b,
    const float* __restrict__ v_s, const float* __restrict__ v_t)
{
    int idx = blockIdx.x * blockDim.x + threadIdx.x;
    if (idx >= OCQKV * DIM) return;
    int oc = idx / DIM, c = idx - oc * DIM;
    float w, s;
    if (oc < 256) {
        w = q_w[oc * DIM + c]; s = q_s[oc] * SCALE_ATTN;
        if (c == 0) g_bqkv[oc] = (q_b[oc] * q_s[oc] + q_t[oc]) * SCALE_ATTN;
    } else if (oc < 512) {
        int o = oc - 256;
        w = k_w[o * DIM + c]; s = k_s[o];
        if (c == 0) g_bqkv[oc] = k_b[o] * k_s[o] + k_t[o];
    } else {
        int o = oc - 512;
        w = v_w[o * DIM + c]; s = v_s[o];
        if (c == 0) g_bqkv[oc] = v_b[o] * v_s[o] + v_t[o];
    }
    g_wqkv[idx] = __float2half_rn(w * s);
}

__global__ void fold_proj_kernel(
    const float* __restrict__ p_w, const float* __restrict__ p_b,
    const float* __restrict__ p_s, const float* __restrict__ p_t)
{
    int idx = blockIdx.x * blockDim.x + threadIdx.x;
    if (idx >= DIM * DH) return;
    int oc = idx / DH;
    g_wproj[idx] = __float2half_rn(p_w[idx] * p_s[oc]);
    if ((idx - oc * DH) == 0) g_bproj[oc] = p_b[oc] * p_s[oc] + p_t[oc];
}

__global__ void fold_vl_kernel(
    const float* __restrict__ vl_w, const float* __restrict__ vl_b,
    const float* __restrict__ vl_s, const float* __restrict__ vl_t)
{
    int idx = blockIdx.x * blockDim.x + threadIdx.x;
    if (idx >= DH * 9) return;
    int ch = idx / 9;
    g_wvl[idx] = vl_w[idx] * vl_s[ch];
    if (idx == ch * 9) g_bvl[ch] = vl_b[ch] * vl_s[ch] + vl_t[ch];
}

__global__ void bias_expand_kernel(const float* __restrict__ bias_seg,
                                   const int* __restrict__ bias_idxs, int n_off)
{
    int e = blockIdx.x * blockDim.x + threadIdx.x;
    if (e >= HEADS * NPIX * NPIX) return;
    int h = e / (NPIX * NPIX), nm = e - h * (NPIX * NPIX);
    g_bias[e] = bias_seg[h * n_off + bias_idxs[nm]];
}

// ---------------- QKV GEMM ----------------
__global__ __launch_bounds__(512, 1)
void gemm_qkv()
{
    __shared__ uint32_t sW32[2 * 128 * WST];
    __shared__ uint32_t sX32[2 * 16 * XST];

    const int b = blockIdx.x, oc0 = blockIdx.y * 128;
    const uint32_t* Xp = g_xp32 + (size_t)b * 192 * NPIX;

    const int tid = threadIdx.x, lane = tid & 31, w = tid >> 5;
    const int ocg = w >> 1, half_ = w & 1, g = lane >> 2, q = lane & 3;
    const int ob = ocg * 16;

    for (int e = tid; e < 2 * 16 * 16; e += 512) {
        int buf = e >> 8, rem = e & 255;
        sX32[(buf * 16 + (rem >> 4)) * XST + 196 + (rem & 15)] = 0u;
    }

    uint32_t sWb = (uint32_t)__cvta_generic_to_shared(sW32);
    uint32_t sXb = (uint32_t)__cvta_generic_to_shared(sX32);

    float c[13][4];
    #pragma unroll
    for (int t = 0; t < 13; ++t) { c[t][0] = c[t][1] = c[t][2] = c[t][3] = 0.f; }

    gemm_stage(g_wqkv, DIM, Xp, oc0, 0, 0, sWb, sXb, tid);
    int buf = 0;
    for (int it = 0; it < DIM / 32; ++it) {
        if (it + 1 < DIM / 32) { gemm_stage(g_wqkv, DIM, Xp, oc0, it + 1, buf ^ 1, sWb, sXb, tid); CP_WAIT(1); }
        else                   { CP_WAIT(0); }
        __syncthreads();
        const uint32_t* cW = sW32 + buf * 128 * WST;
        const uint32_t* cX = sX32 + buf * 16 * XST;
        #pragma unroll
        for (int s = 0; s < 2; ++s) {
            uint32_t a0 = cW[(ob + g) * WST + 8 * s + q];
            uint32_t a1 = cW[(ob + g + 8) * WST + 8 * s + q];
            uint32_t a2 = cW[(ob + g) * WST + 8 * s + q + 4];
            uint32_t a3 = cW[(ob + g + 8) * WST + 8 * s + q + 4];
            #pragma unroll
            for (int t = 0; t < 13; ++t) {
                int n = (half_ * 13 + t) * 8 + g;
                mma16(c[t], a0, a1, a2, a3,
                      cX[(8 * s + q) * XST + n], cX[(8 * s + q + 4) * XST + n]);
            }
        }
        __syncthreads();
        buf ^= 1;
    }

    int r1 = oc0 + ob + g, r2 = r1 + 8;
    float bb1 = g_bqkv[r1], bb2 = g_bqkv[r2];
    if (oc0 < 512) {
        __half* hb = (__half*)((oc0 < 256 ? g_qp32 : g_kp32) + (size_t)b * 128 * 208);
        int cl1 = r1 & 255, cl2 = cl1 + 8;
        #pragma unroll
        for (int t = 0; t < 13; ++t) {
            int n0 = (half_ * 13 + t) * 8 + 2 * q;
            if (n0 < NPIX) {
                hb[((cl1 >> 1) * 208 + n0) * 2 + (cl1 & 1)]     = __float2half_rn(c[t][0] + bb1);
                hb[((cl1 >> 1) * 208 + n0 + 1) * 2 + (cl1 & 1)] = __float2half_rn(c[t][1] + bb1);
                hb[((cl2 >> 1) * 208 + n0) * 2 + (cl2 & 1)]     = __float2half_rn(c[t][2] + bb2);
                hb[((cl2 >> 1) * 208 + n0 + 1) * 2 + (cl2 & 1)] = __float2half_rn(c[t][3] + bb2);
            }
        }
    } else {
        int d1 = r1 - 512, d2 = d1 + 8;
        float* vf = g_vf + (size_t)b * DH * NPIX;
        uint32_t* vp = g_vp32 + (size_t)b * 104 * DH;
        #pragma unroll
        for (int t = 0; t < 13; ++t) {
            int n0 = (half_ * 13 + t) * 8 + 2 * q;
            if (n0 < NPIX) {
                float v0 = c[t][0] + bb1, v1 = c[t][1] + bb1;
                float v2 = c[t][2] + bb2, v3 = c[t][3] + bb2;
                *(float2*)(vf + (size_t)d1 * NPIX + n0) = make_float2(v0, v1);
                *(float2*)(vf + (size_t)d2 * NPIX + n0) = make_float2(v2, v3);
                vp[(size_t)(n0 >> 1) * DH + d1] = packh2(v0, v1);
                vp[(size_t)(n0 >> 1) * DH + d2] = packh2(v2, v3);
            }
        }
    }
}

// ---------------- projection GEMM ----------------
__global__ __launch_bounds__(512, 1)
void gemm_proj(float* __restrict__ Yout)
{
    __shared__ uint32_t sW32[2 * 128 * WST];
    __shared__ uint32_t sX32[2 * 16 * XST];

    const int b = blockIdx.x, oc0 = blockIdx.y * 128;
    const uint32_t* Xp = g_xop32 + (size_t)b * 512 * NPIX;
    float* Yb = Yout + (size_t)b * DIM * NPIX;

    const int tid = threadIdx.x, lane = tid & 31, w = tid >> 5;
    const int ocg = w >> 1, half_ = w & 1, g = lane >> 2, q = lane & 3;
    const int ob = ocg * 16;

    for (int e = tid; e < 2 * 16 * 16; e += 512) {
        int buf = e >> 8, rem = e & 255;
        sX32[(buf * 16 + (rem >> 4)) * XST + 196 + (rem & 15)] = 0u;
    }

    uint32_t sWb = (uint32_t)__cvta_generic_to_shared(sW32);
    uint32_t sXb = (uint32_t)__cvta_generic_to_shared(sX32);

    float c[13][4];
    #pragma unroll
    for (int t = 0; t < 13; ++t) { c[t][0] = c[t][1] = c[t][2] = c[t][3] = 0.f; }

    gemm_stage(g_wproj, DH, Xp, oc0, 0, 0, sWb, sXb, tid);
    int buf = 0;
    for (int it = 0; it < DH / 32; ++it) {
        if (it + 1 < DH / 32) { gemm_stage(g_wproj, DH, Xp, oc0, it + 1, buf ^ 1, sWb, sXb, tid); CP_WAIT(1); }
        else                  { CP_WAIT(0); }
        __syncthreads();
        const uint32_t* cW = sW32 + buf * 128 * WST;
        const uint32_t* cX = sX32 + buf * 16 * XST;
        #pragma unroll
        for (int s = 0; s < 2; ++s) {
            uint32_t a0 = cW[(ob + g) * WST + 8 * s + q];
            uint32_t a1 = cW[(ob + g + 8) * WST + 8 * s + q];
            uint32_t a2 = cW[(ob + g) * WST + 8 * s + q + 4];
            uint32_t a3 = cW[(ob + g + 8) * WST + 8 * s + q + 4];
            #pragma unroll
            for (int t = 0; t < 13; ++t) {
                int n = (half_ * 13 + t) * 8 + g;
                mma16(c[t], a0, a1, a2, a3,
                      cX[(8 * s + q) * XST + n], cX[(8 * s + q + 4) * XST + n]);
            }
        }
        __syncthreads();
        buf ^= 1;
    }

    int r1 = oc0 + ob + g, r2 = r1 + 8;
    float bb1 = g_bproj[r1], bb2 = g_bproj[r2];
    #pragma unroll
    for (int t = 0; t < 13; ++t) {
        int n0 = (half_ * 13 + t) * 8 + 2 * q;
        if (n0 < NPIX) {
            *(float2*)(Yb + (size_t)r1 * NPIX + n0) = make_float2(c[t][0] + bb1, c[t][1] + bb1);
            *(float2*)(Yb + (size_t)r2 * NPIX + n0) = make_float2(c[t][2] + bb2, c[t][3] + bb2);
        }
    }
}

// ---------------- depthwise 3x3 local-V (paired output) ----------------
__global__ __launch_bounds__(224)
void vloc_kernel()
{
    int blk = blockIdx.x;
    int b = blk >> 10, ch = blk & 1023;
    __shared__ float sp[NPIX];
    __shared__ float swv[9];
    int t = threadIdx.x;
    const float* src = g_vf + (size_t)b * DH * NPIX + (size_t)ch * NPIX;
    if (t < NPIX) sp[t] = src[t];
    if (t < 9)  swv[t] = g_wvl[ch * 9 + t];
    __syncthreads();
    if (t < NPIX) {
        int i = t / RES, j = t - i * RES;
        float acc = g_bvl[ch];
        #pragma unroll
        for (int di = 0; di < 3; ++di) {
            int ii = i + di - 1;
            if (ii < 0 || ii >= RES) continue;
            #pragma unroll
            for (int dj = 0; dj < 3; ++dj) {
                int jj = j + dj - 1;
                if (jj < 0 || jj >= RES) continue;
                acc += sp[ii * RES + jj] * swv[di * 3 + dj];
            }
        }
        g_vlp[(((size_t)b * 512 + (ch >> 1)) * NPIX + t) * 2 + (ch & 1)] = acc;
    }
}

// ---------------- fused attention (fp16 mma) ----------------
#define ATTN_SMEM ((HEADS * QT * SP) * 4 + (HEADS * QT * PST) * 4)

__global__ __launch_bounds__(512, 1)
void attn_mma(const float* __restrict__ th1_w, const float* __restrict__ th1_b,
              const float* __restrict__ th2_w, const float* __restrict__ th2_b)
{
    extern __shared__ float sS[];                        // [8][16][SP] fp32 logits/probs
    uint32_t* sP = (uint32_t*)(sS + HEADS * QT * SP);    // [8][16][PST] half2-packed P
    __shared__ float sTh1[64], sTh1b[8], sTh2[64], sTh2b[8];

    const int tile = blockIdx.x, b = blockIdx.y;
    const int nq0 = tile * QT;
    const int tid = threadIdx.x, lane = tid & 31, w = tid >> 5;
    const int h = w >> 1, half_ = w & 1, g = lane >> 2, q = lane & 3;

    if (tid < 64) { sTh1[tid] = th1_w[tid]; sTh2[tid] = th2_w[tid]; }
    if (tid < 8)  { sTh1b[tid] = th1_b[tid]; sTh2b[tid] = th2_b[tid]; }

    // ---- S = Q^T K + bias ----
    {
        const uint32_t* qp = g_qp32 + (size_t)b * 128 * 208;
        const uint32_t* kp = g_kp32 + (size_t)b * 128 * 208;
        float c[13][4];
        #pragma unroll
        for (int t = 0; t < 13; ++t) { c[t][0] = c[t][1] = c[t][2] = c[t][3] = 0.f; }
        #pragma unroll
        for (int s = 0; s < 2; ++s) {
            int row  = (h * 16 + 8 * s + q) * 208;
            int row4 = (h * 16 + 8 * s + q + 4) * 208;
            uint32_t a0 = qp[row + nq0 + g];
            uint32_t a1 = qp[row + nq0 + g + 8];
            uint32_t a2 = qp[row4 + nq0 + g];
            uint32_t a3 = qp[row4 + nq0 + g + 8];
            #pragma unroll
            for (int t = 0; t < 13; ++t) {
                int key = (half_ * 13 + t) * 8 + g;
                mma16(c[t], a0, a1, a2, a3, kp[row + key], kp[row4 + key]);
            }
        }
        float* sh = sS + h * QT * SP;
        const float* bh = g_bias + h * NPIX * NPIX;
        #pragma unroll
        for (int t = 0; t < 13; ++t) {
            int m0 = (half_ * 13 + t) * 8 + 2 * q;
            int r1 = nq0 + g, r2 = nq0 + g + 8;
            float v0 = c[t][0], v1 = c[t][1], v2 = c[t][2], v3 = c[t][3];
            if (m0 < NPIX) {
                if (r1 < NPIX) { v0 += bh[r1 * NPIX + m0]; v1 += bh[r1 * NPIX + m0 + 1]; }
                if (r2 < NPIX) { v2 += bh[r2 * NPIX + m0]; v3 += bh[r2 * NPIX + m0 + 1]; }
            } else { v0 = v1 = v2 = v3 = 0.f; }
            sh[g * SP + m0]       = v0;  sh[g * SP + m0 + 1]       = v1;
            sh[(g + 8) * SP + m0] = v2;  sh[(g + 8) * SP + m0 + 1] = v3;
        }
    }
    __syncthreads();

    // ---- talking-heads mix #1 ----
    for (int e = tid; e < QT * NPIX; e += 512) {
        int r = e / NPIX, m = e - r * NPIX;
        float sv[8];
        #pragma unroll
        for (int i = 0; i < 8; ++i) sv[i] = sS[(i * QT + r) * SP + m];
        #pragma unroll
        for (int o = 0; o < 8; ++o) {
            float a = sTh1b[o];
            #pragma unroll
            for (int i = 0; i < 8; ++i) a += sTh1[o * 8 + i] * sv[i];
            sS[(o * QT + r) * SP + m] = a;
        }
    }
    __syncthreads();

    // ---- softmax ----
    for (int rr = 0; rr < 8; ++rr) {
        float* p = sS + (h * QT + half_ * 8 + rr) * SP;
        float mx = -1e30f;
        for (int m = lane; m < NPIX; m += 32) mx = fmaxf(mx, p[m]);
        #pragma unroll
        for (int o = 16; o; o >>= 1) mx = fmaxf(mx, __shfl_xor_sync(~0u, mx, o));
        float s = 0.f;
        for (int m = lane; m < NPIX; m += 32) { float ev = __expf(p[m] - mx); p[m] = ev; s += ev; }
        #pragma unroll
        for (int o = 16; o; o >>= 1) s += __shfl_xor_sync(~0u, s, o);
        float inv = 1.f / s;
        for (int m = lane; m < NPIX; m += 32) p[m] *= inv;
    }
    __syncthreads();

    // ---- talking-heads mix #2 -> packed half2 P ----
    for (int e = tid; e < QT * 104; e += 512) {
        int r = e / 104, mp = e - r * 104;
        if (mp < 98) {
            int m0 = 2 * mp;
            float sv0[8], sv1[8];
            #pragma unroll
            for (int i = 0; i < 8; ++i) {
                sv0[i] = sS[(i * QT + r) * SP + m0];
                sv1[i] = sS[(i * QT + r) * SP + m0 + 1];
            }
            #pragma unroll
            for (int o = 0; o < 8; ++o) {
                float a0 = sTh2b[o], a1 = sTh2b[o];
                #pragma unroll
                for (int i = 0; i < 8; ++i) {
                    a0 += sTh2[o * 8 + i] * sv0[i];
                    a1 += sTh2[o * 8 + i] * sv1[i];
                }
                sP[(o * QT + r) * PST + mp] = packh2(a0, a1);
            }
        } else {
            #pragma unroll
            for (int o = 0; o < 8; ++o) sP[(o * QT + r) * PST + mp] = 0u;
        }
    }
    __syncthreads();

    // ---- out = P @ V, fused +vloc +relu -> half2 xout [chpair][n] ----
    {
        const uint32_t* vp = g_vp32 + (size_t)b * 104 * DH;
        float c2[8][4];
        #pragma unroll
        for (int t = 0; t < 8; ++t) { c2[t][0] = c2[t][1] = c2[t][2] = c2[t][3] = 0.f; }
        #pragma unroll
        for (int j = 0; j < 13; ++j) {
            uint32_t a0 = sP[(h * QT + g) * PST + 8 * j + q];
            uint32_t a1 = sP[(h * QT + g + 8) * PST + 8 * j + q];
            uint32_t a2 = sP[(h * QT + g) * PST + 8 * j + q + 4];
            uint32_t a3 = sP[(h * QT + g + 8) * PST + 8 * j + q + 4];
            const uint32_t* v0 = vp + (size_t)(8 * j + q) * DH;
            const uint32_t* v4 = vp + (size_t)(8 * j + q + 4) * DH;
            #pragma unroll
            for (int t = 0; t < 8; ++t) {
                int ch = h * DV + (half_ * 8 + t) * 8 + g;
                mma16(c2[t], a0, a1, a2, a3, v0[ch], v4[ch]);
            }
        }
        int r1 = nq0 + g, r2 = nq0 + g + 8;
        #pragma unroll
        for (int t = 0; t < 8; ++t) {
            int cp = h * 64 + (half_ * 8 + t) * 4 + q;
            const float* vl = g_vlp + ((size_t)b * 512 + cp) * NPIX * 2;
            uint32_t* xo = g_xop32 + ((size_t)b * 512 + cp) * NPIX;
            if (r1 < NPIX) {
                float u0 = fmaxf(c2[t][0] + vl[r1 * 2], 0.f);
                float u1 = fmaxf(c2[t][1] + vl[r1 * 2 + 1], 0.f);
                xo[r1] = packh2(u0, u1);
            }
            if (r2 < NPIX) {
                float u2 = fmaxf(c2[t][2] + vl[r2 * 2], 0.f);
                float u3 = fmaxf(c2[t][3] + vl[r2 * 2 + 1], 0.f);
                xo[r2] = packh2(u2, u3);
            }
        }
    }
}

// ---------------- host launch ----------------
extern "C" void kernel_launch(void* const* d_in, const int* in_sizes, int n_in,
                              void* d_out, int out_size)
{
    const float* x        = (const float*)d_in[0];
    const float* q_w      = (const float*)d_in[1];
    const float* q_b      = (const float*)d_in[2];
    const float* q_s      = (const float*)d_in[3];
    const float* q_t      = (const float*)d_in[4];
    const float* k_w      = (const float*)d_in[5];
    const float* k_b      = (const float*)d_in[6];
    const float* k_s      = (const float*)d_in[7];
    const float* k_t      = (const float*)d_in[8];
    const float* v_w      = (const float*)d_in[9];
    const float* v_b      = (const float*)d_in[10];
    const float* v_s      = (const float*)d_in[11];
    const float* v_t      = (const float*)d_in[12];
    const float* vl_w     = (const float*)d_in[13];
    const float* vl_b     = (const float*)d_in[14];
    const float* vl_s     = (const float*)d_in[15];
    const float* vl_t     = (const float*)d_in[16];
    const float* th1_w    = (const float*)d_in[17];
    const float* th1_b    = (const float*)d_in[18];
    const float* th2_w    = (const float*)d_in[19];
    const float* th2_b    = (const float*)d_in[20];
    const float* proj_w   = (const float*)d_in[21];
    const float* proj_b   = (const float*)d_in[22];
    const float* proj_s   = (const float*)d_in[23];
    const float* proj_t   = (const float*)d_in[24];
    const float* bias_seg = (const float*)d_in[25];
    const int*   bias_idx = (const int*)  d_in[26];
    float*       out      = (float*)d_out;

    const int n_off = in_sizes[25] / HEADS;

    cudaFuncSetAttribute(attn_mma, cudaFuncAttributeMaxDynamicSharedMemorySize, ATTN_SMEM);

    // gemm_qkv kept at 4th launch (ncu profiled slot)
    x_prep_kernel<<<(BATCH * 192 * NPIX + 255) / 256, 256>>>(x);
    fold_qkv_kernel<<<(OCQKV * DIM + 255) / 256, 256>>>(q_w, q_b, q_s, q_t,
                                                        k_w, k_b, k_s, k_t,
                                                        v_w, v_b, v_s, v_t);
    pad_zero_kernel<<<(BATCH * 9216 + 255) / 256, 256>>>();

    gemm_qkv<<<dim3(BATCH, OCQKV / 128), 512>>>();      // 4th launch

    fold_proj_kernel<<<(DIM * DH + 255) / 256, 256>>>(proj_w, proj_b, proj_s, proj_t);
    fold_vl_kernel<<<(DH * 9 + 255) / 256, 256>>>(vl_w, vl_b, vl_s, vl_t);
    bias_expand_kernel<<<(HEADS * NPIX * NPIX + 255) / 256, 256>>>(bias_seg, bias_idx, n_off);

    vloc_kernel<<<BATCH * DH, 224>>>();

    attn_mma<<<dim3(QTILES, BATCH), 512, ATTN_SMEM>>>(th1_w, th1_b, th2_w, th2_b);

    gemm_proj<<<dim3(BATCH, DIM / 128), 512>>>(out);
}

// round 9
// speedup vs baseline: 2.7426x; 1.1348x over previous
#include <cuda_runtime.h>
#include <cuda_fp16.h>
#include <cstdint>

// ---------------- problem constants ----------------
#define BATCH   128
#define DIM     384
#define RES     14
#define NPIX    196
#define HEADS   8
#define KD      32
#define DV      128
#define DH      1024
#define OCQKV   1536
#define SCALE_ATTN 0.17677669529663687f
#define QT      16
#define QTILES  13
#define SP      208        // S row stride (floats) in attn smem
#define PST     105        // P half2 row stride (words) in attn smem

// ---------------- device scratch (16B-aligned for cp.async / vector access) ----------------
__device__ __align__(16) __half   g_wqkv [OCQKV * DIM];
__device__ float    g_bqkv [OCQKV];
__device__ __align__(16) __half   g_wproj[DIM * DH];
__device__ float    g_bproj[DIM];
__device__ float    g_wvl  [DH * 9];
__device__ float    g_bvl  [DH];
__device__ float    g_bias [HEADS * NPIX * NPIX];
__device__ __align__(16) uint32_t g_xp32 [(size_t)BATCH * 192 * NPIX];     // x half2-pairs [b][cpair][n]
__device__ __align__(16) uint32_t g_qp32 [(size_t)BATCH * 128 * 208];      // Q [b][cpair][n(208)]
__device__ __align__(16) uint32_t g_kp32 [(size_t)BATCH * 128 * 208];      // K [b][cpair][n(208)]
__device__ __align__(16) uint32_t g_vp32 [(size_t)BATCH * 104 * DH];       // V [b][mpair(104)][ch]
__device__ __align__(16) float    g_vf   [(size_t)BATCH * DH * NPIX];      // V float (vloc input)
__device__ __align__(16) __half   g_vlh  [(size_t)BATCH * 512 * NPIX * 2]; // vloc half paired [b][chpair][n][2]
__device__ __align__(16) uint32_t g_xop32[(size_t)BATCH * 512 * NPIX];     // xout half2 [b][chpair][n]

// ---------------- helpers ----------------
__device__ __forceinline__ uint32_t packh2(float lo, float hi) {
    __half2 h = __floats2half2_rn(lo, hi);
    return *(uint32_t*)&h;
}
__device__ __forceinline__ void mma16(float* c, uint32_t a0, uint32_t a1, uint32_t a2, uint32_t a3,
                                      uint32_t b0, uint32_t b1) {
    asm volatile(
        "mma.sync.aligned.m16n8k16.row.col.f32.f16.f16.f32 "
        "{%0,%1,%2,%3},{%4,%5,%6,%7},{%8,%9},{%0,%1,%2,%3};"
        : "+f"(c[0]), "+f"(c[1]), "+f"(c[2]), "+f"(c[3])
        : "r"(a0), "r"(a1), "r"(a2), "r"(a3), "r"(b0), "r"(b1));
}
__device__ __forceinline__ void cp16(uint32_t smem_dst, const void* gsrc) {
    asm volatile("cp.async.cg.shared.global [%0], [%1], 16;" :: "r"(smem_dst), "l"(gsrc));
}
#define CP_COMMIT()  asm volatile("cp.async.commit_group;")
#define CP_WAIT(n)   asm volatile("cp.async.wait_group %0;" :: "n"(n))

#define WST 20     // W smem row stride (words)  — bank-clean (20 mod 32 pattern distinct)
#define XST 136    // X smem row stride (words)  — 136 ≡ 8 (mod 32): conflict-free q-rows

// ---------------- prep kernels ----------------
__global__ void x_prep_kernel(const float* __restrict__ x)
{
    int idx = blockIdx.x * blockDim.x + threadIdx.x;
    if (idx >= BATCH * 192 * NPIX) return;
    int n = idx % NPIX, cp = (idx / NPIX) % 192, b = idx / (NPIX * 192);
    const float* xr = x + ((size_t)b * DIM + 2 * cp) * NPIX + n;
    g_xp32[idx] = packh2(xr[0], xr[NPIX]);
}

__global__ void pad_zero_kernel()
{
    int idx = blockIdx.x * blockDim.x + threadIdx.x;
    if (idx >= BATCH * 9216) return;
    int b = idx / 9216, i = idx % 9216;
    if (i < 1536) {
        int cp = i / 12, ni = i % 12;
        g_qp32[((size_t)b * 128 + cp) * 208 + 196 + ni] = 0u;
    } else if (i < 3072) {
        int r = i - 1536, cp = r / 12, ni = r % 12;
        g_kp32[((size_t)b * 128 + cp) * 208 + 196 + ni] = 0u;
    } else {
        int r = i - 3072;
        int mp = 98 + r / DH, d = r % DH;
        g_vp32[(size_t)b * 104 * DH + (size_t)mp * DH + d] = 0u;
    }
}

// ---------------- BN folding ----------------
__global__ void fold_qkv_kernel(
    const float* __restrict__ q_w, const float* __restrict__ q_b,
    const float* __restrict__ q_s, const float* __restrict__ q_t,
    const float* __restrict__ k_w, const float* __restrict__ k_b,
    const float* __restrict__ k_s, const float* __restrict__ k_t,
    const float* __restrict__ v_w, const float* __restrict__ v_b,
    const float* __restrict__ v_s, const float* __restrict__ v_t)
{
    int idx = blockIdx.x * blockDim.x + threadIdx.x;
    if (idx >= OCQKV * DIM) return;
    int oc = idx / DIM, c = idx - oc * DIM;
    float w, s;
    if (oc < 256) {
        w = q_w[oc * DIM + c]; s = q_s[oc] * SCALE_ATTN;
        if (c == 0) g_bqkv[oc] = (q_b[oc] * q_s[oc] + q_t[oc]) * SCALE_ATTN;
    } else if (oc < 512) {
        int o = oc - 256;
        w = k_w[o * DIM + c]; s = k_s[o];
        if (c == 0) g_bqkv[oc] = k_b[o] * k_s[o] + k_t[o];
    } else {
        int o = oc - 512;
        w = v_w[o * DIM + c]; s = v_s[o];
        if (c == 0) g_bqkv[oc] = v_b[o] * v_s[o] + v_t[o];
    }
    g_wqkv[idx] = __float2half_rn(w * s);
}

__global__ void fold_proj_kernel(
    const float* __restrict__ p_w, const float* __restrict__ p_b,
    const float* __restrict__ p_s, const float* __restrict__ p_t)
{
    int idx = blockIdx.x * blockDim.x + threadIdx.x;
    if (idx >= DIM * DH) return;
    int oc = idx / DH;
    g_wproj[idx] = __float2half_rn(p_w[idx] * p_s[oc]);
    if ((idx - oc * DH) == 0) g_bproj[oc] = p_b[oc] * p_s[oc] + p_t[oc];
}

__global__ void fold_vl_kernel(
    const float* __restrict__ vl_w, const float* __restrict__ vl_b,
    const float* __restrict__ vl_s, const float* __restrict__ vl_t)
{
    int idx = blockIdx.x * blockDim.x + threadIdx.x;
    if (idx >= DH * 9) return;
    int ch = idx / 9;
    g_wvl[idx] = vl_w[idx] * vl_s[ch];
    if (idx == ch * 9) g_bvl[ch] = vl_b[ch] * vl_s[ch] + vl_t[ch];
}

__global__ void bias_expand_kernel(const float* __restrict__ bias_seg,
                                   const int* __restrict__ bias_idxs, int n_off)
{
    int e = blockIdx.x * blockDim.x + threadIdx.x;
    if (e >= HEADS * NPIX * NPIX) return;
    int h = e / (NPIX * NPIX), nm = e - h * (NPIX * NPIX);
    g_bias[e] = bias_seg[h * n_off + bias_idxs[nm]];
}

// ---------------- fp16 GEMM core: 256-thread CTA, tile 128oc x 104n, 2 CTAs/SM ----------------
// warp w = oc group (16 rows); all 8 warps cover the full 104-n half (13 n8 tiles).
// stage one 32-k tile: W 128x4 chunks, X 16 pair-rows x (26|23) chunks
__device__ __forceinline__ void gemm_stage(const __half* W, int ldw, const uint32_t* Xp,
                                           int oc0, int nh, int it, int buf,
                                           uint32_t sWb, uint32_t sXb, int tid)
{
    int k0 = it * 32;
    #pragma unroll
    for (int e = tid; e < 512; e += 256) {
        int oc = e >> 2, cc = e & 3;
        cp16(sWb + (((buf * 128) + oc) * WST + cc * 4) * 4,
             W + (size_t)(oc0 + oc) * ldw + k0 + cc * 8);
    }
    int cnt = nh ? 23 : 26;                 // nh1: cols 92..103 are global pad (prezeroed)
    for (int e = tid; e < 16 * cnt; e += 256) {
        int pr = e / cnt, cc = e - pr * cnt;
        cp16(sXb + ((buf * 16 + pr) * XST + cc * 4) * 4,
             Xp + (size_t)(it * 16 + pr) * NPIX + nh * 104 + cc * 4);
    }
    CP_COMMIT();
}

// MODE 0: QKV (K=DIM, X=g_xp32), MODE 1: proj (K=DH, X=g_xop32, Y=d_out)
template<int MODE>
__global__ __launch_bounds__(256, 2)
void gemm_mma(float* __restrict__ Yout)
{
    __shared__ uint32_t sW32[2 * 128 * WST];
    __shared__ uint32_t sX32[2 * 16 * XST];

    const int K = (MODE == 0) ? DIM : DH;
    const __half* Wh = (MODE == 0) ? g_wqkv : g_wproj;
    const int b = blockIdx.x, oc0 = blockIdx.y * 128, nh = blockIdx.z;
    const uint32_t* Xp = ((MODE == 0) ? g_xp32 : g_xop32) + (size_t)b * (K / 2) * NPIX;

    const int tid = threadIdx.x, lane = tid & 31, w = tid >> 5;
    const int g = lane >> 2, q = lane & 3;
    const int ob = w * 16;

    // prezero X cols 92..103 (global pad region) — only written for nh==1 path
    if (nh) {
        for (int e = tid; e < 2 * 16 * 12; e += 256) {
            int buf = e / 192, rem = e % 192;
            sX32[(buf * 16 + rem / 12) * XST + 92 + rem % 12] = 0u;
        }
        __syncthreads();
    }

    uint32_t sWb = (uint32_t)__cvta_generic_to_shared(sW32);
    uint32_t sXb = (uint32_t)__cvta_generic_to_shared(sX32);

    float c[13][4];
    #pragma unroll
    for (int t = 0; t < 13; ++t) { c[t][0] = c[t][1] = c[t][2] = c[t][3] = 0.f; }

    gemm_stage(Wh, K, Xp, oc0, nh, 0, 0, sWb, sXb, tid);
    int buf = 0;
    const int NIT = K / 32;
    for (int it = 0; it < NIT; ++it) {
        if (it + 1 < NIT) { gemm_stage(Wh, K, Xp, oc0, nh, it + 1, buf ^ 1, sWb, sXb, tid); CP_WAIT(1); }
        else              { CP_WAIT(0); }
        __syncthreads();
        const uint32_t* cW = sW32 + buf * 128 * WST;
        const uint32_t* cX = sX32 + buf * 16 * XST;
        #pragma unroll
        for (int s = 0; s < 2; ++s) {
            uint32_t a0 = cW[(ob + g) * WST + 8 * s + q];
            uint32_t a1 = cW[(ob + g + 8) * WST + 8 * s + q];
            uint32_t a2 = cW[(ob + g) * WST + 8 * s + q + 4];
            uint32_t a3 = cW[(ob + g + 8) * WST + 8 * s + q + 4];
            #pragma unroll
            for (int t = 0; t < 13; ++t) {
                int n = t * 8 + g;
                mma16(c[t], a0, a1, a2, a3,
                      cX[(8 * s + q) * XST + n], cX[(8 * s + q + 4) * XST + n]);
            }
        }
        __syncthreads();
        buf ^= 1;
    }

    int r1 = oc0 + ob + g, r2 = r1 + 8;
    if (MODE == 1) {
        float bb1 = g_bproj[r1], bb2 = g_bproj[r2];
        float* Yb = Yout + (size_t)b * DIM * NPIX;
        #pragma unroll
        for (int t = 0; t < 13; ++t) {
            int n0 = nh * 104 + t * 8 + 2 * q;
            if (n0 < NPIX) {
                *(float2*)(Yb + (size_t)r1 * NPIX + n0) = make_float2(c[t][0] + bb1, c[t][1] + bb1);
                *(float2*)(Yb + (size_t)r2 * NPIX + n0) = make_float2(c[t][2] + bb2, c[t][3] + bb2);
            }
        }
    } else {
        float bb1 = g_bqkv[r1], bb2 = g_bqkv[r2];
        if (oc0 < 512) {
            __half* hb = (__half*)((oc0 < 256 ? g_qp32 : g_kp32) + (size_t)b * 128 * 208);
            int cl1 = r1 & 255, cl2 = cl1 + 8;
            #pragma unroll
            for (int t = 0; t < 13; ++t) {
                int n0 = nh * 104 + t * 8 + 2 * q;
                if (n0 < NPIX) {
                    hb[((cl1 >> 1) * 208 + n0) * 2 + (cl1 & 1)]     = __float2half_rn(c[t][0] + bb1);
                    hb[((cl1 >> 1) * 208 + n0 + 1) * 2 + (cl1 & 1)] = __float2half_rn(c[t][1] + bb1);
                    hb[((cl2 >> 1) * 208 + n0) * 2 + (cl2 & 1)]     = __float2half_rn(c[t][2] + bb2);
                    hb[((cl2 >> 1) * 208 + n0 + 1) * 2 + (cl2 & 1)] = __float2half_rn(c[t][3] + bb2);
                }
            }
        } else {
            int d1 = r1 - 512, d2 = d1 + 8;
            float* vf = g_vf + (size_t)b * DH * NPIX;
            uint32_t* vp = g_vp32 + (size_t)b * 104 * DH;
            #pragma unroll
            for (int t = 0; t < 13; ++t) {
                int n0 = nh * 104 + t * 8 + 2 * q;
                if (n0 < NPIX) {
                    float v0 = c[t][0] + bb1, v1 = c[t][1] + bb1;
                    float v2 = c[t][2] + bb2, v3 = c[t][3] + bb2;
                    *(float2*)(vf + (size_t)d1 * NPIX + n0) = make_float2(v0, v1);
                    *(float2*)(vf + (size_t)d2 * NPIX + n0) = make_float2(v2, v3);
                    vp[(size_t)(n0 >> 1) * DH + d1] = packh2(v0, v1);
                    vp[(size_t)(n0 >> 1) * DH + d2] = packh2(v2, v3);
                }
            }
        }
    }
}

// ---------------- depthwise 3x3 local-V (half paired output) ----------------
__global__ __launch_bounds__(224)
void vloc_kernel()
{
    int blk = blockIdx.x;
    int b = blk >> 10, ch = blk & 1023;
    __shared__ float sp[NPIX];
    __shared__ float swv[9];
    int t = threadIdx.x;
    const float* src = g_vf + (size_t)b * DH * NPIX + (size_t)ch * NPIX;
    if (t < NPIX) sp[t] = src[t];
    if (t < 9)  swv[t] = g_wvl[ch * 9 + t];
    __syncthreads();
    if (t < NPIX) {
        int i = t / RES, j = t - i * RES;
        float acc = g_bvl[ch];
        #pragma unroll
        for (int di = 0; di < 3; ++di) {
            int ii = i + di - 1;
            if (ii < 0 || ii >= RES) continue;
            #pragma unroll
            for (int dj = 0; dj < 3; ++dj) {
                int jj = j + dj - 1;
                if (jj < 0 || jj >= RES) continue;
                acc += sp[ii * RES + jj] * swv[di * 3 + dj];
            }
        }
        g_vlh[(((size_t)b * 512 + (ch >> 1)) * NPIX + t) * 2 + (ch & 1)] = __float2half_rn(acc);
    }
}

// ---------------- fused attention (fp16 mma) ----------------
#define ATTN_SMEM ((HEADS * QT * SP) * 4 + (HEADS * QT * PST) * 4)

__global__ __launch_bounds__(512, 1)
void attn_mma(const float* __restrict__ th1_w, const float* __restrict__ th1_b,
              const float* __restrict__ th2_w, const float* __restrict__ th2_b)
{
    extern __shared__ float sS[];                        // [8][16][SP] fp32 logits/probs
    uint32_t* sP = (uint32_t*)(sS + HEADS * QT * SP);    // [8][16][PST] half2-packed P
    __shared__ float sTh1[64], sTh1b[8], sTh2[64], sTh2b[8];

    const int tile = blockIdx.x, b = blockIdx.y;
    const int nq0 = tile * QT;
    const int tid = threadIdx.x, lane = tid & 31, w = tid >> 5;
    const int h = w >> 1, half_ = w & 1, g = lane >> 2, q = lane & 3;

    if (tid < 64) { sTh1[tid] = th1_w[tid]; sTh2[tid] = th2_w[tid]; }
    if (tid < 8)  { sTh1b[tid] = th1_b[tid]; sTh2b[tid] = th2_b[tid]; }

    // ---- S = Q^T K + bias ----
    {
        const uint32_t* qp = g_qp32 + (size_t)b * 128 * 208;
        const uint32_t* kp = g_kp32 + (size_t)b * 128 * 208;
        float c[13][4];
        #pragma unroll
        for (int t = 0; t < 13; ++t) { c[t][0] = c[t][1] = c[t][2] = c[t][3] = 0.f; }
        #pragma unroll
        for (int s = 0; s < 2; ++s) {
            int row  = (h * 16 + 8 * s + q) * 208;
            int row4 = (h * 16 + 8 * s + q + 4) * 208;
            uint32_t a0 = qp[row + nq0 + g];
            uint32_t a1 = qp[row + nq0 + g + 8];
            uint32_t a2 = qp[row4 + nq0 + g];
            uint32_t a3 = qp[row4 + nq0 + g + 8];
            #pragma unroll
            for (int t = 0; t < 13; ++t) {
                int key = (half_ * 13 + t) * 8 + g;
                mma16(c[t], a0, a1, a2, a3, kp[row + key], kp[row4 + key]);
            }
        }
        float* sh = sS + h * QT * SP;
        const float* bh = g_bias + h * NPIX * NPIX;
        #pragma unroll
        for (int t = 0; t < 13; ++t) {
            int m0 = (half_ * 13 + t) * 8 + 2 * q;
            int r1 = nq0 + g, r2 = nq0 + g + 8;
            float v0 = c[t][0], v1 = c[t][1], v2 = c[t][2], v3 = c[t][3];
            if (m0 < NPIX) {
                if (r1 < NPIX) { v0 += bh[r1 * NPIX + m0]; v1 += bh[r1 * NPIX + m0 + 1]; }
                if (r2 < NPIX) { v2 += bh[r2 * NPIX + m0]; v3 += bh[r2 * NPIX + m0 + 1]; }
            } else { v0 = v1 = v2 = v3 = 0.f; }
            sh[g * SP + m0]       = v0;  sh[g * SP + m0 + 1]       = v1;
            sh[(g + 8) * SP + m0] = v2;  sh[(g + 8) * SP + m0 + 1] = v3;
        }
    }
    __syncthreads();

    // ---- talking-heads mix #1 ----
    for (int e = tid; e < QT * NPIX; e += 512) {
        int r = e / NPIX, m = e - r * NPIX;
        float sv[8];
        #pragma unroll
        for (int i = 0; i < 8; ++i) sv[i] = sS[(i * QT + r) * SP + m];
        #pragma unroll
        for (int o = 0; o < 8; ++o) {
            float a = sTh1b[o];
            #pragma unroll
            for (int i = 0; i < 8; ++i) a += sTh1[o * 8 + i] * sv[i];
            sS[(o * QT + r) * SP + m] = a;
        }
    }
    __syncthreads();

    // ---- softmax ----
    for (int rr = 0; rr < 8; ++rr) {
        float* p = sS + (h * QT + half_ * 8 + rr) * SP;
        float mx = -1e30f;
        for (int m = lane; m < NPIX; m += 32) mx = fmaxf(mx, p[m]);
        #pragma unroll
        for (int o = 16; o; o >>= 1) mx = fmaxf(mx, __shfl_xor_sync(~0u, mx, o));
        float s = 0.f;
        for (int m = lane; m < NPIX; m += 32) { float ev = __expf(p[m] - mx); p[m] = ev; s += ev; }
        #pragma unroll
        for (int o = 16; o; o >>= 1) s += __shfl_xor_sync(~0u, s, o);
        float inv = 1.f / s;
        for (int m = lane; m < NPIX; m += 32) p[m] *= inv;
    }
    __syncthreads();

    // ---- talking-heads mix #2 -> packed half2 P ----
    for (int e = tid; e < QT * 104; e += 512) {
        int r = e / 104, mp = e - r * 104;
        if (mp < 98) {
            int m0 = 2 * mp;
            float sv0[8], sv1[8];
            #pragma unroll
            for (int i = 0; i < 8; ++i) {
                sv0[i] = sS[(i * QT + r) * SP + m0];
                sv1[i] = sS[(i * QT + r) * SP + m0 + 1];
            }
            #pragma unroll
            for (int o = 0; o < 8; ++o) {
                float a0 = sTh2b[o], a1 = sTh2b[o];
                #pragma unroll
                for (int i = 0; i < 8; ++i) {
                    a0 += sTh2[o * 8 + i] * sv0[i];
                    a1 += sTh2[o * 8 + i] * sv1[i];
                }
                sP[(o * QT + r) * PST + mp] = packh2(a0, a1);
            }
        } else {
            #pragma unroll
            for (int o = 0; o < 8; ++o) sP[(o * QT + r) * PST + mp] = 0u;
        }
    }
    __syncthreads();

    // ---- out = P @ V, fused +vloc +relu -> half2 xout [chpair][n] ----
    {
        const uint32_t* vp = g_vp32 + (size_t)b * 104 * DH;
        float c2[8][4];
        #pragma unroll
        for (int t = 0; t < 8; ++t) { c2[t][0] = c2[t][1] = c2[t][2] = c2[t][3] = 0.f; }
        #pragma unroll
        for (int j = 0; j < 13; ++j) {
            uint32_t a0 = sP[(h * QT + g) * PST + 8 * j + q];
            uint32_t a1 = sP[(h * QT + g + 8) * PST + 8 * j + q];
            uint32_t a2 = sP[(h * QT + g) * PST + 8 * j + q + 4];
            uint32_t a3 = sP[(h * QT + g + 8) * PST + 8 * j + q + 4];
            const uint32_t* v0 = vp + (size_t)(8 * j + q) * DH;
            const uint32_t* v4 = vp + (size_t)(8 * j + q + 4) * DH;
            #pragma unroll
            for (int t = 0; t < 8; ++t) {
                int ch = h * DV + (half_ * 8 + t) * 8 + g;
                mma16(c2[t], a0, a1, a2, a3, v0[ch], v4[ch]);
            }
        }
        int r1 = nq0 + g, r2 = nq0 + g + 8;
        #pragma unroll
        for (int t = 0; t < 8; ++t) {
            int cp = h * 64 + (half_ * 8 + t) * 4 + q;
            const uint32_t* vl = (const uint32_t*)g_vlh + ((size_t)b * 512 + cp) * NPIX;
            uint32_t* xo = g_xop32 + ((size_t)b * 512 + cp) * NPIX;
            if (r1 < NPIX) {
                uint32_t wv = vl[r1]; __half2 hv = *(__half2*)&wv;
                float u0 = fmaxf(c2[t][0] + __low2float(hv), 0.f);
                float u1 = fmaxf(c2[t][1] + __high2float(hv), 0.f);
                xo[r1] = packh2(u0, u1);
            }
            if (r2 < NPIX) {
                uint32_t wv = vl[r2]; __half2 hv = *(__half2*)&wv;
                float u2 = fmaxf(c2[t][2] + __low2float(hv), 0.f);
                float u3 = fmaxf(c2[t][3] + __high2float(hv), 0.f);
                xo[r2] = packh2(u2, u3);
            }
        }
    }
}

// ---------------- host launch ----------------
extern "C" void kernel_launch(void* const* d_in, const int* in_sizes, int n_in,
                              void* d_out, int out_size)
{
    const float* x        = (const float*)d_in[0];
    const float* q_w      = (const float*)d_in[1];
    const float* q_b      = (const float*)d_in[2];
    const float* q_s      = (const float*)d_in[3];
    const float* q_t      = (const float*)d_in[4];
    const float* k_w      = (const float*)d_in[5];
    const float* k_b      = (const float*)d_in[6];
    const float* k_s      = (const float*)d_in[7];
    const float* k_t      = (const float*)d_in[8];
    const float* v_w      = (const float*)d_in[9];
    const float* v_b      = (const float*)d_in[10];
    const float* v_s      = (const float*)d_in[11];
    const float* v_t      = (const float*)d_in[12];
    const float* vl_w     = (const float*)d_in[13];
    const float* vl_b     = (const float*)d_in[14];
    const float* vl_s     = (const float*)d_in[15];
    const float* vl_t     = (const float*)d_in[16];
    const float* th1_w    = (const float*)d_in[17];
    const float* th1_b    = (const float*)d_in[18];
    const float* th2_w    = (const float*)d_in[19];
    const float* th2_b    = (const float*)d_in[20];
    const float* proj_w   = (const float*)d_in[21];
    const float* proj_b   = (const float*)d_in[22];
    const float* proj_s   = (const float*)d_in[23];
    const float* proj_t   = (const float*)d_in[24];
    const float* bias_seg = (const float*)d_in[25];
    const int*   bias_idx = (const int*)  d_in[26];
    float*       out      = (float*)d_out;

    const int n_off = in_sizes[25] / HEADS;

    cudaFuncSetAttribute(attn_mma, cudaFuncAttributeMaxDynamicSharedMemorySize, ATTN_SMEM);

    // gemm_mma<0> kept at 4th launch (ncu profiled slot)
    x_prep_kernel<<<(BATCH * 192 * NPIX + 255) / 256, 256>>>(x);
    fold_qkv_kernel<<<(OCQKV * DIM + 255) / 256, 256>>>(q_w, q_b, q_s, q_t,
                                                        k_w, k_b, k_s, k_t,
                                                        v_w, v_b, v_s, v_t);
    pad_zero_kernel<<<(BATCH * 9216 + 255) / 256, 256>>>();

    gemm_mma<0><<<dim3(BATCH, OCQKV / 128, 2), 256>>>(nullptr);   // 4th launch

    fold_proj_kernel<<<(DIM * DH + 255) / 256, 256>>>(proj_w, proj_b, proj_s, proj_t);
    fold_vl_kernel<<<(DH * 9 + 255) / 256, 256>>>(vl_w, vl_b, vl_s, vl_t);
    bias_expand_kernel<<<(HEADS * NPIX * NPIX + 255) / 256, 256>>>(bias_seg, bias_idx, n_off);

    vloc_kernel<<<BATCH * DH, 224>>>();

    attn_mma<<<dim3(QTILES, BATCH), 512, ATTN_SMEM>>>(th1_w, th1_b, th2_w, th2_b);

    gemm_mma<1><<<dim3(BATCH, DIM / 128, 2), 256>>>(out);
}